// round 2
// baseline (speedup 1.0000x reference)
#include <cuda_runtime.h>
#include <math.h>

#define NIMG   16
#define NCLS   80
#define KSEL   1000
#define NCAND  3000
#define NPICK  100
#define HWTOT  13125
#define MTOT   1050000

// Output layout (float32, concatenated tuple: boxes, scores, classes, keep)
#define OFS_BOX 0
#define OFS_SC  (NIMG*NPICK*4)          // 6400
#define OFS_CL  (OFS_SC + NIMG*NPICK)   // 8000
#define OFS_KP  (OFS_CL + NIMG*NPICK)   // 9600

// ---------------- scratch (device globals, no allocation) ----------------
__device__ unsigned g_keys[(size_t)NIMG * MTOT];   // 67.2 MB score keys
__device__ float    g_ctrsig[NIMG * HWTOT];
__device__ unsigned g_h1[NIMG*3*2048];
__device__ unsigned g_h2[NIMG*3*2048];
__device__ unsigned g_h3[NIMG*3*1024];
__device__ unsigned g_pfx1[NIMG*3];
__device__ unsigned g_krem1[NIMG*3];
__device__ unsigned g_pfx21[NIMG*3];
__device__ unsigned g_krem2[NIMG*3];
__device__ unsigned g_T[NIMG*3];
__device__ unsigned g_allow[NIMG*3];
__device__ unsigned g_cnt[NIMG*3];
__device__ unsigned g_tie[NIMG*3];
__device__ float4   g_cbox[NIMG*NCAND];
__device__ float    g_csc[NIMG*NCAND];
__device__ int      g_ccls[NIMG*NCAND];

__device__ __forceinline__ float sigm(float x) { return 1.0f / (1.0f + expf(-x)); }

// ---------------- init: zero hists/counters, invalidate candidates ----------------
__global__ void init_kernel()
{
    int i = blockIdx.x * blockDim.x + threadIdx.x;
    int st = gridDim.x * blockDim.x;
    for (int j = i; j < NIMG*3*2048; j += st) { g_h1[j] = 0; g_h2[j] = 0; }
    for (int j = i; j < NIMG*3*1024; j += st) g_h3[j] = 0;
    for (int j = i; j < NIMG*3; j += st) { g_cnt[j] = 0; g_tie[j] = 0; }
    for (int j = i; j < NIMG*NCAND; j += st) {
        g_csc[j] = -1.0f; g_ccls[j] = 0;
        g_cbox[j] = make_float4(0.f, 0.f, 0.f, 0.f);
    }
}

// ---------------- precompute sigmoid(centerness) ----------------
__global__ void ctr_kernel(const float* __restrict__ c0, const float* __restrict__ c1,
                           const float* __restrict__ c2)
{
    int i = blockIdx.x * blockDim.x + threadIdx.x;
    if (i >= NIMG * HWTOT) return;
    int n = i / HWTOT, r = i % HWTOT;
    float v;
    if (r < 10000)      v = c0[n*10000 + r];
    else if (r < 12500) v = c1[n*2500  + (r - 10000)];
    else                v = c2[n*625   + (r - 12500)];
    g_ctrsig[i] = sigm(v);
}

// ---------------- pass 1: score -> key store + top-11-bit histogram ----------------
__global__ void score_hist_kernel(const float* __restrict__ cls, int level,
                                  int HW, int keyofs, int ctrofs)
{
    __shared__ unsigned sh[2048];
    int n = blockIdx.y;
    for (int i = threadIdx.x; i < 2048; i += blockDim.x) sh[i] = 0;
    __syncthreads();

    const int M = NCLS * HW;
    const float* clsn = cls + (size_t)n * M;
    const float* ct   = g_ctrsig + n * HWTOT + ctrofs;
    unsigned* keys    = g_keys + (size_t)n * MTOT + keyofs;

    int stride = gridDim.x * blockDim.x;
    for (int hw = blockIdx.x * blockDim.x + threadIdx.x; hw < HW; hw += stride) {
        float t = ct[hw];
        #pragma unroll 8
        for (int c = 0; c < NCLS; ++c) {
            float s = sigm(clsn[c*HW + hw]);
            unsigned key = 0;
            if (s > 0.05f) key = __float_as_uint(s * t);   // score>0 -> key>0
            keys[c*HW + hw] = key;
            if (key) {
                unsigned bin = key >> 21;
                unsigned m = __match_any_sync(__activemask(), bin);
                if ((threadIdx.x & 31) == (__ffs(m) - 1))
                    atomicAdd(&sh[bin], __popc(m));
            }
        }
    }
    __syncthreads();
    unsigned* gh = g_h1 + (n*3 + level) * 2048;
    for (int i = threadIdx.x; i < 2048; i += blockDim.x)
        if (sh[i]) atomicAdd(&gh[i], sh[i]);
}

// ---------------- generic block select over a histogram ----------------
__device__ void block_select(const unsigned* h, int nbins, unsigned target,
                             int* r_bin, unsigned* r_krem, int* r_found)
{
    __shared__ unsigned sh[2048];
    __shared__ unsigned gsum[64];
    int tid = threadIdx.x;
    for (int i = tid; i < nbins; i += blockDim.x) sh[i] = h[i];
    __syncthreads();
    int ngroups = nbins / 32;
    if (tid < ngroups) {
        unsigned s = 0;
        for (int j = 0; j < 32; ++j) s += sh[tid*32 + j];
        gsum[tid] = s;
    }
    __syncthreads();
    if (tid == 0) {
        unsigned cum = 0; int found = 0;
        for (int g = ngroups - 1; g >= 0; --g) {
            if (cum + gsum[g] >= target) {
                for (int b = g*32 + 31; b >= g*32; --b) {
                    unsigned c = sh[b];
                    if (cum + c >= target) { *r_bin = b; *r_krem = target - cum; found = 1; break; }
                    cum += c;
                }
                break;
            }
            cum += gsum[g];
        }
        *r_found = found;
    }
    __syncthreads();
}

__global__ void select1_kernel()
{
    int si = blockIdx.x;
    __shared__ int rb, rf; __shared__ unsigned rk;
    block_select(g_h1 + si*2048, 2048, KSEL, &rb, &rk, &rf);
    if (threadIdx.x == 0) {
        if (rf) { g_pfx1[si] = (unsigned)rb; g_krem1[si] = rk; }
        else    { g_pfx1[si] = 0xFFFFFFFFu; g_T[si] = 0; g_allow[si] = 0; g_pfx21[si] = 0xFFFFFFFFu; }
    }
}

__global__ void hist2_kernel(int level, int M, int keyofs)
{
    __shared__ unsigned sh[2048];
    int n = blockIdx.y; int si = n*3 + level;
    unsigned pfx = g_pfx1[si];
    for (int i = threadIdx.x; i < 2048; i += blockDim.x) sh[i] = 0;
    __syncthreads();
    const unsigned* keys = g_keys + (size_t)n * MTOT + keyofs;
    int stride = gridDim.x * blockDim.x;
    for (int i = blockIdx.x * blockDim.x + threadIdx.x; i < M; i += stride) {
        unsigned key = keys[i];
        if (key && (key >> 21) == pfx) atomicAdd(&sh[(key >> 10) & 0x7FF], 1);
    }
    __syncthreads();
    unsigned* gh = g_h2 + si * 2048;
    for (int i = threadIdx.x; i < 2048; i += blockDim.x)
        if (sh[i]) atomicAdd(&gh[i], sh[i]);
}

__global__ void select2_kernel()
{
    int si = blockIdx.x;
    __shared__ int rb, rf; __shared__ unsigned rk;
    unsigned pfx1 = g_pfx1[si];
    if (pfx1 == 0xFFFFFFFFu) return;
    block_select(g_h2 + si*2048, 2048, g_krem1[si], &rb, &rk, &rf);
    if (threadIdx.x == 0) {
        if (rf) { g_pfx21[si] = (pfx1 << 11) | (unsigned)rb; g_krem2[si] = rk; }
        else    { g_pfx21[si] = 0xFFFFFFFFu; g_T[si] = 0; g_allow[si] = 0; }
    }
}

__global__ void hist3_kernel(int level, int M, int keyofs)
{
    __shared__ unsigned sh[1024];
    int n = blockIdx.y; int si = n*3 + level;
    unsigned pfx = g_pfx21[si];
    for (int i = threadIdx.x; i < 1024; i += blockDim.x) sh[i] = 0;
    __syncthreads();
    const unsigned* keys = g_keys + (size_t)n * MTOT + keyofs;
    int stride = gridDim.x * blockDim.x;
    for (int i = blockIdx.x * blockDim.x + threadIdx.x; i < M; i += stride) {
        unsigned key = keys[i];
        if (key && (key >> 10) == pfx) atomicAdd(&sh[key & 0x3FF], 1);
    }
    __syncthreads();
    unsigned* gh = g_h3 + si * 1024;
    for (int i = threadIdx.x; i < 1024; i += blockDim.x)
        if (sh[i]) atomicAdd(&gh[i], sh[i]);
}

__global__ void select3_kernel()
{
    int si = blockIdx.x;
    __shared__ int rb, rf; __shared__ unsigned rk;
    unsigned pfx21 = g_pfx21[si];
    if (pfx21 == 0xFFFFFFFFu) return;
    block_select(g_h3 + si*1024, 1024, g_krem2[si], &rb, &rk, &rf);
    if (threadIdx.x == 0) {
        if (rf) { g_T[si] = (pfx21 << 10) | (unsigned)rb; g_allow[si] = rk; }
        else    { g_T[si] = 0; g_allow[si] = 0; }
    }
}

// ---------------- compact + decode boxes for selected candidates ----------------
__global__ void compact_kernel(const float* __restrict__ reg, const float* __restrict__ loc,
                               int level, int HW, int keyofs, float stride_f, int cand_base)
{
    int n = blockIdx.y; int si = n*3 + level;
    const int M = NCLS * HW;
    unsigned T = g_T[si];
    unsigned allow = g_allow[si];
    const unsigned* keys = g_keys + (size_t)n * MTOT + keyofs;
    const float* rg = reg + (size_t)n * 4 * HW;
    int gstride = gridDim.x * blockDim.x;
    for (int pos = blockIdx.x * blockDim.x + threadIdx.x; pos < M; pos += gstride) {
        unsigned key = keys[pos];
        if (!key) continue;
        bool take = key > T;
        if (!take && key == T && allow) take = (atomicAdd(&g_tie[si], 1u) < allow);
        if (!take) continue;
        unsigned slot = atomicAdd(&g_cnt[si], 1u);
        int hw = pos % HW;
        int c  = pos / HW;
        float l = rg[hw]        * stride_f;
        float t = rg[HW + hw]   * stride_f;
        float r = rg[2*HW + hw] * stride_f;
        float b = rg[3*HW + hw] * stride_f;
        float x = loc[2*hw], y = loc[2*hw + 1];
        float x1 = fminf(fmaxf(x - l, 0.f), 800.f);
        float y1 = fminf(fmaxf(y - t, 0.f), 800.f);
        float x2 = fminf(fmaxf(x + r, 0.f), 800.f);
        float y2 = fminf(fmaxf(y + b, 0.f), 800.f);
        int g = n * NCAND + cand_base + (int)slot;
        g_cbox[g] = make_float4(x1, y1, x2, y2);
        g_csc[g]  = sqrtf(__uint_as_float(key));
        g_ccls[g] = c + 1;
    }
}

// ---------------- greedy NMS (one block per image) ----------------
__global__ void nms_kernel(float* __restrict__ out)
{
    extern __shared__ unsigned char smraw[];
    float* ox1 = (float*)smraw;
    float* oy1 = ox1 + NCAND;
    float* ox2 = oy1 + NCAND;
    float* oy2 = ox2 + NCAND;
    float* oar = oy2 + NCAND;
    float* osc = oar + NCAND;
    int*   ocl = (int*)(osc + NCAND);

    __shared__ float rs[32]; __shared__ int ri[32];
    __shared__ float sB; __shared__ int sI;

    int n = blockIdx.x;
    int tid = threadIdx.x;

    for (int i = tid; i < NCAND; i += blockDim.x) {
        float s = g_csc[n*NCAND + i];
        float4 b = g_cbox[n*NCAND + i];
        int c = g_ccls[n*NCAND + i];
        float x1, y1, x2, y2, a;
        if (s > 0.f) {
            float off = (float)c * 4096.0f;
            x1 = b.x + off; y1 = b.y + off; x2 = b.z + off; y2 = b.w + off;
            a = (x2 - x1) * (y2 - y1);
        } else {
            s = -1.0f; x1 = y1 = x2 = y2 = a = 0.f;
        }
        ox1[i] = x1; oy1[i] = y1; ox2[i] = x2; oy2[i] = y2;
        oar[i] = a;  osc[i] = s;  ocl[i] = c;
    }
    __syncthreads();

    for (int it = 0; it < NPICK; ++it) {
        float bs = -2.0f; int bi = NCAND;
        for (int i = tid; i < NCAND; i += blockDim.x) {
            float s = osc[i];
            if (s > bs || (s == bs && i < bi)) { bs = s; bi = i; }
        }
        #pragma unroll
        for (int o = 16; o; o >>= 1) {
            float s2 = __shfl_down_sync(0xFFFFFFFFu, bs, o);
            int   i2 = __shfl_down_sync(0xFFFFFFFFu, bi, o);
            if (s2 > bs || (s2 == bs && i2 < bi)) { bs = s2; bi = i2; }
        }
        if ((tid & 31) == 0) { rs[tid >> 5] = bs; ri[tid >> 5] = bi; }
        __syncthreads();
        if (tid == 0) {
            float s = rs[0]; int b = ri[0];
            int nw = blockDim.x >> 5;
            for (int w = 1; w < nw; ++w)
                if (rs[w] > s || (rs[w] == s && ri[w] < b)) { s = rs[w]; b = ri[w]; }
            sB = s; sI = b;
        }
        __syncthreads();
        bs = sB; bi = sI;
        bool keep = bs > 0.0f;

        if (tid < 7) {
            int row = n * NPICK + it;
            if (tid < 4)       out[OFS_BOX + row*4 + tid] = keep ? ((const float*)&g_cbox[n*NCAND + bi])[tid] : 0.f;
            else if (tid == 4) out[OFS_SC + row] = keep ? bs : 0.f;
            else if (tid == 5) out[OFS_CL + row] = keep ? (float)ocl[bi] : 0.f;
            else               out[OFS_KP + row] = keep ? 1.0f : 0.f;
        }

        float px1 = ox1[bi], py1 = oy1[bi], px2 = ox2[bi], py2 = oy2[bi], pa = oar[bi];
        for (int i = tid; i < NCAND; i += blockDim.x) {
            if (i == bi) { osc[i] = -1.0f; continue; }
            float xx1 = fmaxf(px1, ox1[i]);
            float yy1 = fmaxf(py1, oy1[i]);
            float xx2 = fminf(px2, ox2[i]);
            float yy2 = fminf(py2, oy2[i]);
            float inter = fmaxf(xx2 - xx1, 0.f) * fmaxf(yy2 - yy1, 0.f);
            float iou = inter / (oar[i] + pa - inter + 1e-9f);
            if (iou > 0.6f) osc[i] = -1.0f;
        }
        __syncthreads();
    }
}

// ---------------- launch ----------------
extern "C" void kernel_launch(void* const* d_in, const int* in_sizes, int n_in,
                              void* d_out, int out_size)
{
    // Input order: setup_inputs() dict order is per-level
    //   (locations_l, box_cls_l, box_regression_l, centerness_l) for l = 0,1,2.
    // Hedge: detect via in_sizes (cls0 has 12.8M elements). If d_in[1] is cls0
    // we are in dict order; otherwise fall back to reference-signature order.
    const float *loc0, *loc1, *loc2, *cls0, *cls1, *cls2;
    const float *reg0, *reg1, *reg2, *ctr0, *ctr1, *ctr2;
    if (in_sizes[1] == 16 * 80 * 10000) {
        // dict order
        loc0 = (const float*)d_in[0];  cls0 = (const float*)d_in[1];
        reg0 = (const float*)d_in[2];  ctr0 = (const float*)d_in[3];
        loc1 = (const float*)d_in[4];  cls1 = (const float*)d_in[5];
        reg1 = (const float*)d_in[6];  ctr1 = (const float*)d_in[7];
        loc2 = (const float*)d_in[8];  cls2 = (const float*)d_in[9];
        reg2 = (const float*)d_in[10]; ctr2 = (const float*)d_in[11];
    } else {
        // signature order
        loc0 = (const float*)d_in[0];  loc1 = (const float*)d_in[1];  loc2 = (const float*)d_in[2];
        cls0 = (const float*)d_in[3];  cls1 = (const float*)d_in[4];  cls2 = (const float*)d_in[5];
        reg0 = (const float*)d_in[6];  reg1 = (const float*)d_in[7];  reg2 = (const float*)d_in[8];
        ctr0 = (const float*)d_in[9];  ctr1 = (const float*)d_in[10]; ctr2 = (const float*)d_in[11];
    }
    float* out = (float*)d_out;

    const int HW0 = 10000, HW1 = 2500, HW2 = 625;
    const int M0 = 800000, M1 = 200000, M2 = 50000;
    const int K0 = 0, K1 = 800000, K2 = 1000000;

    cudaFuncSetAttribute(nms_kernel, cudaFuncAttributeMaxDynamicSharedMemorySize, 7 * NCAND * 4);

    init_kernel<<<512, 256>>>();
    ctr_kernel<<<(NIMG*HWTOT + 255) / 256, 256>>>(ctr0, ctr1, ctr2);

    score_hist_kernel<<<dim3(40, NIMG), 256>>>(cls0, 0, HW0, K0, 0);
    score_hist_kernel<<<dim3(10, NIMG), 256>>>(cls1, 1, HW1, K1, 10000);
    score_hist_kernel<<<dim3(3,  NIMG), 256>>>(cls2, 2, HW2, K2, 12500);
    select1_kernel<<<NIMG*3, 256>>>();

    hist2_kernel<<<dim3(128, NIMG), 256>>>(0, M0, K0);
    hist2_kernel<<<dim3(32,  NIMG), 256>>>(1, M1, K1);
    hist2_kernel<<<dim3(8,   NIMG), 256>>>(2, M2, K2);
    select2_kernel<<<NIMG*3, 256>>>();

    hist3_kernel<<<dim3(128, NIMG), 256>>>(0, M0, K0);
    hist3_kernel<<<dim3(32,  NIMG), 256>>>(1, M1, K1);
    hist3_kernel<<<dim3(8,   NIMG), 256>>>(2, M2, K2);
    select3_kernel<<<NIMG*3, 256>>>();

    compact_kernel<<<dim3(128, NIMG), 256>>>(reg0, loc0, 0, HW0, K0, 8.0f,  0);
    compact_kernel<<<dim3(32,  NIMG), 256>>>(reg1, loc1, 1, HW1, K1, 16.0f, KSEL);
    compact_kernel<<<dim3(8,   NIMG), 256>>>(reg2, loc2, 2, HW2, K2, 32.0f, 2*KSEL);

    nms_kernel<<<NIMG, 1024, 7 * NCAND * 4>>>(out);
}

// round 3
// speedup vs baseline: 1.3039x; 1.3039x over previous
#include <cuda_runtime.h>
#include <math.h>

#define NIMG   16
#define NCLS   80
#define KSEL   1000
#define NCAND  3000
#define NPICK  100
#define HWTOT  13125
#define MTOT   1050000
#define CAP    131072

// Output layout (float32, concatenated tuple: boxes, scores, classes, keep)
#define OFS_BOX 0
#define OFS_SC  (NIMG*NPICK*4)
#define OFS_CL  (OFS_SC + NIMG*NPICK)
#define OFS_KP  (OFS_CL + NIMG*NPICK)

// ---------------- scratch (device globals, no allocation) ----------------
__device__ unsigned g_keys[(size_t)NIMG * MTOT];        // 67.2 MB score keys
__device__ float    g_ctrsig[NIMG * HWTOT];
__device__ unsigned g_h1[NIMG*3*2048];
__device__ unsigned g_F[NIMG*3];
__device__ unsigned g_colcnt[NIMG*3];
__device__ unsigned g_colkey[(size_t)NIMG*3*CAP];       // 25.2 MB
__device__ unsigned g_colpos[(size_t)NIMG*3*CAP];       // 25.2 MB
__device__ float4   g_cbox[NIMG*NCAND];
__device__ float    g_csc[NIMG*NCAND];
__device__ int      g_ccls[NIMG*NCAND];

__device__ __forceinline__ float sigm(float x) { return 1.0f / (1.0f + expf(-x)); }

// ---------------- init: zero hists/counters, invalidate candidates, ctr sigmoid --------
__global__ void init_kernel(const float* __restrict__ c0, const float* __restrict__ c1,
                            const float* __restrict__ c2)
{
    int i0 = blockIdx.x * blockDim.x + threadIdx.x;
    int st = gridDim.x * blockDim.x;
    for (int j = i0; j < NIMG*3*2048; j += st) g_h1[j] = 0;
    for (int j = i0; j < NIMG*3; j += st) g_colcnt[j] = 0;
    for (int j = i0; j < NIMG*NCAND; j += st) {
        g_csc[j] = -1.0f; g_ccls[j] = 0;
        g_cbox[j] = make_float4(0.f, 0.f, 0.f, 0.f);
    }
    for (int j = i0; j < NIMG*HWTOT; j += st) {
        int n = j / HWTOT, r = j - n * HWTOT;
        float v;
        if (r < 10000)      v = c0[n*10000 + r];
        else if (r < 12500) v = c1[n*2500  + (r - 10000)];
        else                v = c2[n*625   + (r - 12500)];
        g_ctrsig[j] = sigm(v);
    }
}

// ---------------- pass 1: fused score -> key store + top-11-bit histogram ----------------
template<int HW, int CTROFS>
__device__ __forceinline__ void proc4(int eloc, const float* __restrict__ clsl,
                                      unsigned* __restrict__ keydst,
                                      const float* __restrict__ ctrn,
                                      unsigned* sh, bool useShared, unsigned* ghist)
{
    float4 v = *reinterpret_cast<const float4*>(clsl + eloc);
    float vv[4] = {v.x, v.y, v.z, v.w};
    unsigned k4[4];
    #pragma unroll
    for (int j = 0; j < 4; ++j) {
        int e = eloc + j;
        int c = e / HW;
        int hw = e - c * HW;
        float s = sigm(vv[j]);
        float t = ctrn[CTROFS + hw];
        k4[j] = (s > 0.05f) ? __float_as_uint(s * t) : 0u;
    }
    *reinterpret_cast<uint4*>(keydst) = make_uint4(k4[0], k4[1], k4[2], k4[3]);
    #pragma unroll
    for (int j = 0; j < 4; ++j) {
        unsigned key = k4[j];
        unsigned amask = __activemask();
        unsigned grp = __ballot_sync(amask, key != 0);
        if (key) {
            unsigned bin = key >> 21;
            unsigned m = __match_any_sync(grp, bin);
            if ((int)(threadIdx.x & 31) == (__ffs(m) - 1)) {
                if (useShared) atomicAdd(&sh[bin], (unsigned)__popc(m));
                else           atomicAdd(&ghist[bin], (unsigned)__popc(m));
            }
        }
    }
}

__global__ void pass1_kernel(const float* __restrict__ c0, const float* __restrict__ c1,
                             const float* __restrict__ c2)
{
    __shared__ unsigned sh[2048];
    for (int i = threadIdx.x; i < 2048; i += blockDim.x) sh[i] = 0;
    __syncthreads();

    int n = blockIdx.y;
    int e = (blockIdx.x * blockDim.x + threadIdx.x) * 4;
    int blk_first = blockIdx.x * blockDim.x * 4;
    int blklev = blk_first < 800000 ? 0 : (blk_first < 1000000 ? 1 : 2);
    const float* ctrn = g_ctrsig + n * HWTOT;

    if (e < MTOT) {
        unsigned* kd = g_keys + (size_t)n * MTOT + e;
        if (e < 800000)
            proc4<10000, 0>(e, c0 + (size_t)n*800000, kd, ctrn, sh, blklev == 0,
                            g_h1 + (n*3 + 0)*2048);
        else if (e < 1000000)
            proc4<2500, 10000>(e - 800000, c1 + (size_t)n*200000, kd, ctrn, sh, blklev == 1,
                               g_h1 + (n*3 + 1)*2048);
        else
            proc4<625, 12500>(e - 1000000, c2 + (size_t)n*50000, kd, ctrn, sh, blklev == 2,
                              g_h1 + (n*3 + 2)*2048);
    }
    __syncthreads();
    unsigned* gh = g_h1 + (n*3 + blklev) * 2048;
    for (int i = threadIdx.x; i < 2048; i += blockDim.x)
        if (sh[i]) atomicAdd(&gh[i], sh[i]);
}

// ---------------- select1: per-segment bin floor F of the 1000th key ----------------
__global__ void select1_kernel()
{
    __shared__ unsigned sh[2048];
    __shared__ unsigned gsum[64];
    int seg = blockIdx.x;
    int tid = threadIdx.x;
    for (int i = tid; i < 2048; i += blockDim.x) sh[i] = g_h1[seg*2048 + i];
    __syncthreads();
    if (tid < 64) {
        unsigned s = 0;
        for (int j = 0; j < 32; ++j) s += sh[tid*32 + j];
        gsum[tid] = s;
    }
    __syncthreads();
    if (tid == 0) {
        unsigned total = 0;
        for (int g = 0; g < 64; ++g) total += gsum[g];
        unsigned F = 1;
        if (total >= KSEL) {
            unsigned cum = 0;
            for (int g = 63; g >= 0; --g) {
                if (cum + gsum[g] >= KSEL) {
                    for (int b = g*32 + 31; b >= g*32; --b) {
                        if (cum + sh[b] >= KSEL) { F = ((unsigned)b) << 21; break; }
                        cum += sh[b];
                    }
                    break;
                }
                cum += gsum[g];
            }
        }
        g_F[seg] = F;
    }
}

// ---------------- collect: append (key,pos) with key >= F to per-segment buffers --------
__global__ void collect_kernel()
{
    int n = blockIdx.y;
    int e4 = blockIdx.x * blockDim.x + threadIdx.x;
    int e = e4 * 4;
    if (e >= MTOT) return;
    uint4 k = *reinterpret_cast<const uint4*>(g_keys + (size_t)n * MTOT + e);
    int lev = e < 800000 ? 0 : (e < 1000000 ? 1 : 2);
    int seg = n*3 + lev;
    unsigned F = g_F[seg];
    int base = lev == 0 ? 0 : (lev == 1 ? 800000 : 1000000);
    unsigned kk[4] = {k.x, k.y, k.z, k.w};
    #pragma unroll
    for (int j = 0; j < 4; ++j) {
        unsigned key = kk[j];
        bool take = (key >= F) && (key != 0);
        unsigned amask = __activemask();
        unsigned bal = __ballot_sync(amask, take);
        if (take) {
            unsigned mm = __match_any_sync(bal, seg);
            int leader = __ffs(mm) - 1;
            unsigned rank = __popc(mm & ((1u << (threadIdx.x & 31)) - 1u));
            unsigned basep = 0;
            if ((int)(threadIdx.x & 31) == leader)
                basep = atomicAdd(&g_colcnt[seg], (unsigned)__popc(mm));
            basep = __shfl_sync(mm, basep, leader);
            unsigned idx = basep + rank;
            if (idx < CAP) {
                g_colkey[(size_t)seg*CAP + idx] = key;
                g_colpos[(size_t)seg*CAP + idx] = (unsigned)((e + j) - base);
            }
        }
    }
}

// ---------------- block-level histogram select (descending) ----------------
__device__ __forceinline__ void bsel(unsigned* sh, int nb, unsigned target,
                                     int* r_bin, unsigned* r_krem)
{
    __shared__ unsigned gsum[64];
    int tid = threadIdx.x;
    int ngroups = nb / 32;
    if (tid < ngroups) {
        unsigned s = 0;
        for (int j = 0; j < 32; ++j) s += sh[tid*32 + j];
        gsum[tid] = s;
    }
    __syncthreads();
    if (tid == 0) {
        unsigned cum = 0;
        *r_bin = 0; *r_krem = target;
        for (int g = ngroups - 1; g >= 0; --g) {
            if (cum + gsum[g] >= target) {
                for (int b = g*32 + 31; b >= g*32; --b) {
                    if (cum + sh[b] >= target) { *r_bin = b; *r_krem = target - cum; return; }
                    cum += sh[b];
                }
            }
            cum += gsum[g];
        }
    }
}

// ---------------- seg_select: exact top-1000 within collected list + decode ------------
__global__ void seg_select_kernel(const float* __restrict__ r0, const float* __restrict__ r1,
                                  const float* __restrict__ r2, const float* __restrict__ l0,
                                  const float* __restrict__ l1, const float* __restrict__ l2)
{
    __shared__ unsigned sh[2048];
    __shared__ int s_bin; __shared__ unsigned s_krem;
    __shared__ unsigned s_T, s_allow, s_emit, s_tie;
    int seg = blockIdx.x;
    int n = seg / 3, lev = seg % 3;
    unsigned mraw = g_colcnt[seg];
    int m = (int)(mraw < CAP ? mraw : CAP);
    const unsigned* keys = g_colkey + (size_t)seg*CAP;
    const unsigned* poss = g_colpos + (size_t)seg*CAP;
    int tid = threadIdx.x;

    if (tid == 0) { s_emit = 0; s_tie = 0; }

    if (m <= KSEL) {
        if (tid == 0) { s_T = 0; s_allow = 0; }
        __syncthreads();
    } else {
        // round 1: bits[31:21]
        for (int i = tid; i < 2048; i += blockDim.x) sh[i] = 0;
        __syncthreads();
        for (int i = tid; i < m; i += blockDim.x)
            atomicAdd(&sh[keys[i] >> 21], 1u);
        __syncthreads();
        bsel(sh, 2048, KSEL, &s_bin, &s_krem);
        __syncthreads();
        unsigned b1 = (unsigned)s_bin, want = s_krem;
        // round 2: bits[20:10] among prefix b1
        __syncthreads();
        for (int i = tid; i < 2048; i += blockDim.x) sh[i] = 0;
        __syncthreads();
        for (int i = tid; i < m; i += blockDim.x) {
            unsigned key = keys[i];
            if ((key >> 21) == b1) atomicAdd(&sh[(key >> 10) & 0x7FF], 1u);
        }
        __syncthreads();
        bsel(sh, 2048, want, &s_bin, &s_krem);
        __syncthreads();
        unsigned b2 = (unsigned)s_bin; want = s_krem;
        unsigned pfx2 = (b1 << 11) | b2;
        // round 3: bits[9:0] among prefix pfx2
        __syncthreads();
        for (int i = tid; i < 1024; i += blockDim.x) sh[i] = 0;
        __syncthreads();
        for (int i = tid; i < m; i += blockDim.x) {
            unsigned key = keys[i];
            if ((key >> 10) == pfx2) atomicAdd(&sh[key & 0x3FF], 1u);
        }
        __syncthreads();
        bsel(sh, 1024, want, &s_bin, &s_krem);
        __syncthreads();
        if (tid == 0) { s_T = (pfx2 << 10) | (unsigned)s_bin; s_allow = s_krem; }
        __syncthreads();
    }
    unsigned T = s_T, allow = s_allow;

    const float* rg; const float* lc; int HW; float sf;
    if (lev == 0)      { rg = r0 + (size_t)n*40000; lc = l0; HW = 10000; sf = 8.0f; }
    else if (lev == 1) { rg = r1 + (size_t)n*10000; lc = l1; HW = 2500;  sf = 16.0f; }
    else               { rg = r2 + (size_t)n*2500;  lc = l2; HW = 625;   sf = 32.0f; }

    for (int i = tid; i < m; i += blockDim.x) {
        unsigned key = keys[i];
        bool take;
        if (m <= KSEL) take = true;
        else {
            take = key > T;
            if (!take && key == T && allow) take = (atomicAdd(&s_tie, 1u) < allow);
        }
        if (!take) continue;
        unsigned slot = atomicAdd(&s_emit, 1u);
        unsigned pos = poss[i];
        int c = (int)pos / HW, hw = (int)pos - c * HW;
        float l = rg[hw]        * sf;
        float t = rg[HW + hw]   * sf;
        float r = rg[2*HW + hw] * sf;
        float b = rg[3*HW + hw] * sf;
        float x = lc[2*hw], y = lc[2*hw + 1];
        float x1 = fminf(fmaxf(x - l, 0.f), 800.f);
        float y1 = fminf(fmaxf(y - t, 0.f), 800.f);
        float x2 = fminf(fmaxf(x + r, 0.f), 800.f);
        float y2 = fminf(fmaxf(y + b, 0.f), 800.f);
        int g = n * NCAND + lev * KSEL + (int)slot;
        g_cbox[g] = make_float4(x1, y1, x2, y2);
        g_csc[g]  = sqrtf(__uint_as_float(key));
        g_ccls[g] = c + 1;
    }
}

// ---------------- greedy NMS (one block per image) ----------------
__global__ void nms_kernel(float* __restrict__ out)
{
    extern __shared__ unsigned char smraw[];
    float* ox1 = (float*)smraw;
    float* oy1 = ox1 + NCAND;
    float* ox2 = oy1 + NCAND;
    float* oy2 = ox2 + NCAND;
    float* oar = oy2 + NCAND;
    float* osc = oar + NCAND;
    int*   ocl = (int*)(osc + NCAND);

    __shared__ float rs[32]; __shared__ int ri[32];
    __shared__ float sB; __shared__ int sI;

    int n = blockIdx.x;
    int tid = threadIdx.x;

    for (int i = tid; i < NCAND; i += blockDim.x) {
        float s = g_csc[n*NCAND + i];
        float4 b = g_cbox[n*NCAND + i];
        int c = g_ccls[n*NCAND + i];
        float x1, y1, x2, y2, a;
        if (s > 0.f) {
            float off = (float)c * 4096.0f;
            x1 = b.x + off; y1 = b.y + off; x2 = b.z + off; y2 = b.w + off;
            a = (x2 - x1) * (y2 - y1);
        } else {
            s = -1.0f; x1 = y1 = x2 = y2 = a = 0.f;
        }
        ox1[i] = x1; oy1[i] = y1; ox2[i] = x2; oy2[i] = y2;
        oar[i] = a;  osc[i] = s;  ocl[i] = c;
    }
    __syncthreads();

    for (int it = 0; it < NPICK; ++it) {
        float bs = -2.0f; int bi = NCAND;
        for (int i = tid; i < NCAND; i += blockDim.x) {
            float s = osc[i];
            if (s > bs || (s == bs && i < bi)) { bs = s; bi = i; }
        }
        #pragma unroll
        for (int o = 16; o; o >>= 1) {
            float s2 = __shfl_down_sync(0xFFFFFFFFu, bs, o);
            int   i2 = __shfl_down_sync(0xFFFFFFFFu, bi, o);
            if (s2 > bs || (s2 == bs && i2 < bi)) { bs = s2; bi = i2; }
        }
        if ((tid & 31) == 0) { rs[tid >> 5] = bs; ri[tid >> 5] = bi; }
        __syncthreads();
        if (tid == 0) {
            float s = rs[0]; int b = ri[0];
            int nw = blockDim.x >> 5;
            for (int w = 1; w < nw; ++w)
                if (rs[w] > s || (rs[w] == s && ri[w] < b)) { s = rs[w]; b = ri[w]; }
            sB = s; sI = b;
        }
        __syncthreads();
        bs = sB; bi = sI;
        bool keep = bs > 0.0f;

        if (tid < 7) {
            int row = n * NPICK + it;
            if (tid < 4)       out[OFS_BOX + row*4 + tid] = keep ? ((const float*)&g_cbox[n*NCAND + bi])[tid] : 0.f;
            else if (tid == 4) out[OFS_SC + row] = keep ? bs : 0.f;
            else if (tid == 5) out[OFS_CL + row] = keep ? (float)ocl[bi] : 0.f;
            else               out[OFS_KP + row] = keep ? 1.0f : 0.f;
        }

        float px1 = ox1[bi], py1 = oy1[bi], px2 = ox2[bi], py2 = oy2[bi], pa = oar[bi];
        for (int i = tid; i < NCAND; i += blockDim.x) {
            if (i == bi) { osc[i] = -1.0f; continue; }
            float xx1 = fmaxf(px1, ox1[i]);
            float yy1 = fmaxf(py1, oy1[i]);
            float xx2 = fminf(px2, ox2[i]);
            float yy2 = fminf(py2, oy2[i]);
            float inter = fmaxf(xx2 - xx1, 0.f) * fmaxf(yy2 - yy1, 0.f);
            float iou = inter / (oar[i] + pa - inter + 1e-9f);
            if (iou > 0.6f) osc[i] = -1.0f;
        }
        __syncthreads();
    }
}

// ---------------- launch ----------------
extern "C" void kernel_launch(void* const* d_in, const int* in_sizes, int n_in,
                              void* d_out, int out_size)
{
    const float *loc0, *loc1, *loc2, *cls0, *cls1, *cls2;
    const float *reg0, *reg1, *reg2, *ctr0, *ctr1, *ctr2;
    if (in_sizes[1] == 16 * 80 * 10000) {
        // dict order: per-level (loc, cls, reg, ctr)
        loc0 = (const float*)d_in[0];  cls0 = (const float*)d_in[1];
        reg0 = (const float*)d_in[2];  ctr0 = (const float*)d_in[3];
        loc1 = (const float*)d_in[4];  cls1 = (const float*)d_in[5];
        reg1 = (const float*)d_in[6];  ctr1 = (const float*)d_in[7];
        loc2 = (const float*)d_in[8];  cls2 = (const float*)d_in[9];
        reg2 = (const float*)d_in[10]; ctr2 = (const float*)d_in[11];
    } else {
        // signature order
        loc0 = (const float*)d_in[0];  loc1 = (const float*)d_in[1];  loc2 = (const float*)d_in[2];
        cls0 = (const float*)d_in[3];  cls1 = (const float*)d_in[4];  cls2 = (const float*)d_in[5];
        reg0 = (const float*)d_in[6];  reg1 = (const float*)d_in[7];  reg2 = (const float*)d_in[8];
        ctr0 = (const float*)d_in[9];  ctr1 = (const float*)d_in[10]; ctr2 = (const float*)d_in[11];
    }
    float* out = (float*)d_out;

    cudaFuncSetAttribute(nms_kernel, cudaFuncAttributeMaxDynamicSharedMemorySize, 7 * NCAND * 4);

    const int BLKX = (MTOT/4 + 255) / 256;   // 1026 blocks per image

    init_kernel<<<416, 256>>>(ctr0, ctr1, ctr2);
    pass1_kernel<<<dim3(BLKX, NIMG), 256>>>(cls0, cls1, cls2);
    select1_kernel<<<NIMG*3, 256>>>();
    collect_kernel<<<dim3(BLKX, NIMG), 256>>>();
    seg_select_kernel<<<NIMG*3, 256>>>(reg0, reg1, reg2, loc0, loc1, loc2);
    nms_kernel<<<NIMG, 1024, 7 * NCAND * 4>>>(out);
}

// round 4
// speedup vs baseline: 2.0168x; 1.5468x over previous
#include <cuda_runtime.h>
#include <math.h>

#define NIMG   16
#define NCLS   80
#define KSEL   1000
#define NCAND  3000
#define NPICK  100
#define HWTOT  13125
#define MTOT   1050000
#define NVEC   (MTOT/4)          // 262500
#define CAP    262144

// Output layout (float32, concatenated tuple: boxes, scores, classes, keep)
#define OFS_BOX 0
#define OFS_SC  (NIMG*NPICK*4)
#define OFS_CL  (OFS_SC + NIMG*NPICK)
#define OFS_KP  (OFS_CL + NIMG*NPICK)

// ---------------- scratch (device globals, no allocation) ----------------
__device__ float    g_ctrsig[NIMG * HWTOT];
__device__ unsigned g_h1[NIMG*3*2048];
__device__ unsigned g_F[NIMG*3];
__device__ unsigned g_colcnt[NIMG*3];
__device__ unsigned g_colkey[(size_t)NIMG*3*CAP];
__device__ unsigned g_colpos[(size_t)NIMG*3*CAP];
__device__ float4   g_cbox[NIMG*NCAND];
__device__ float    g_csc[NIMG*NCAND];
__device__ int      g_ccls[NIMG*NCAND];

__device__ __forceinline__ float sigm(float x) { return 1.0f / (1.0f + expf(-x)); }

// ---------------- init: zero hists/counters, invalidate candidates, ctr sigmoid --------
__global__ void init_kernel(const float* __restrict__ c0, const float* __restrict__ c1,
                            const float* __restrict__ c2)
{
    int i0 = blockIdx.x * blockDim.x + threadIdx.x;
    int st = gridDim.x * blockDim.x;
    for (int j = i0; j < NIMG*3*2048; j += st) g_h1[j] = 0;
    for (int j = i0; j < NIMG*3; j += st) g_colcnt[j] = 0;
    for (int j = i0; j < NIMG*NCAND; j += st) {
        g_csc[j] = -1.0f; g_ccls[j] = 0;
        g_cbox[j] = make_float4(0.f, 0.f, 0.f, 0.f);
    }
    for (int j = i0; j < NIMG*HWTOT; j += st) {
        int n = j / HWTOT, r = j - n * HWTOT;
        float v;
        if (r < 10000)      v = c0[n*10000 + r];
        else if (r < 12500) v = c1[n*2500  + (r - 10000)];
        else                v = c2[n*625   + (r - 12500)];
        g_ctrsig[j] = sigm(v);
    }
}

// ---------------- per-vec key computation (compile-time HW) ----------------
template<int HW, int CTROFS>
__device__ __forceinline__ void keys4(int el, const float* __restrict__ src,
                                      const float* __restrict__ ctrn, unsigned k4[4])
{
    float4 v = *reinterpret_cast<const float4*>(src + el);
    float vv[4] = {v.x, v.y, v.z, v.w};
    #pragma unroll
    for (int j = 0; j < 4; ++j) {
        int e = el + j;
        int c = e / HW;
        int hw = e - c * HW;
        float s = sigm(vv[j]);
        float t = ctrn[CTROFS + hw];
        k4[j] = (s > 0.05f) ? __float_as_uint(s * t) : 0u;
    }
}

// ---------------- pass 1: fused score -> 3x2048-bin histogram (no key store) ----------
__global__ __launch_bounds__(256) void pass1_kernel(
    const float* __restrict__ c0, const float* __restrict__ c1, const float* __restrict__ c2)
{
    __shared__ unsigned sh[3*2048];
    for (int i = threadIdx.x; i < 3*2048; i += blockDim.x) sh[i] = 0;
    __syncthreads();

    int n = blockIdx.y;
    const float* ctrn = g_ctrsig + n * HWTOT;
    int vstride = gridDim.x * blockDim.x;

    for (int v = blockIdx.x * blockDim.x + threadIdx.x; v < NVEC; v += vstride) {
        int e = v * 4;
        unsigned k4[4];
        unsigned* shl;
        if (e < 800000) {
            keys4<10000, 0>(e, c0 + (size_t)n*800000, ctrn, k4);
            shl = sh;
        } else if (e < 1000000) {
            keys4<2500, 10000>(e - 800000, c1 + (size_t)n*200000, ctrn, k4);
            shl = sh + 2048;
        } else {
            keys4<625, 12500>(e - 1000000, c2 + (size_t)n*50000, ctrn, k4);
            shl = sh + 4096;
        }
        #pragma unroll
        for (int j = 0; j < 4; ++j)
            if (k4[j]) atomicAdd(&shl[k4[j] >> 21], 1u);
    }
    __syncthreads();
    for (int lev = 0; lev < 3; ++lev) {
        unsigned* gh = g_h1 + (n*3 + lev) * 2048;
        for (int i = threadIdx.x; i < 2048; i += blockDim.x) {
            unsigned c = sh[lev*2048 + i];
            if (c) atomicAdd(&gh[i], c);
        }
    }
}

// ---------------- select1: per-segment bin floor F of the 1000th key ----------------
__global__ void select1_kernel()
{
    __shared__ unsigned sh[2048];
    __shared__ unsigned gsum[64];
    int seg = blockIdx.x;
    int tid = threadIdx.x;
    for (int i = tid; i < 2048; i += blockDim.x) sh[i] = g_h1[seg*2048 + i];
    __syncthreads();
    if (tid < 64) {
        unsigned s = 0;
        for (int j = 0; j < 32; ++j) s += sh[tid*32 + j];
        gsum[tid] = s;
    }
    __syncthreads();
    if (tid == 0) {
        unsigned total = 0;
        for (int g = 0; g < 64; ++g) total += gsum[g];
        unsigned F = 1;
        if (total >= KSEL) {
            unsigned cum = 0;
            for (int g = 63; g >= 0; --g) {
                if (cum + gsum[g] >= KSEL) {
                    for (int b = g*32 + 31; b >= g*32; --b) {
                        if (cum + sh[b] >= KSEL) { F = ((unsigned)b) << 21; break; }
                        cum += sh[b];
                    }
                    break;
                }
                cum += gsum[g];
            }
        }
        g_F[seg] = F;
    }
}

// ---------------- collect: recompute keys, append (key,pos) with key >= F --------------
__global__ __launch_bounds__(256) void collect_kernel(
    const float* __restrict__ c0, const float* __restrict__ c1, const float* __restrict__ c2)
{
    int n = blockIdx.y;
    const float* ctrn = g_ctrsig + n * HWTOT;
    unsigned F0 = g_F[n*3 + 0], F1 = g_F[n*3 + 1], F2 = g_F[n*3 + 2];
    int vstride = gridDim.x * blockDim.x;

    for (int v = blockIdx.x * blockDim.x + threadIdx.x; v < NVEC; v += vstride) {
        int e = v * 4;
        unsigned k4[4];
        int lev, base;
        unsigned F;
        if (e < 800000) {
            keys4<10000, 0>(e, c0 + (size_t)n*800000, ctrn, k4);
            lev = 0; base = 0; F = F0;
        } else if (e < 1000000) {
            keys4<2500, 10000>(e - 800000, c1 + (size_t)n*200000, ctrn, k4);
            lev = 1; base = 800000; F = F1;
        } else {
            keys4<625, 12500>(e - 1000000, c2 + (size_t)n*50000, ctrn, k4);
            lev = 2; base = 1000000; F = F2;
        }
        int seg = n*3 + lev;
        #pragma unroll
        for (int j = 0; j < 4; ++j) {
            unsigned key = k4[j];
            bool take = (key >= F) && (key != 0);
            unsigned amask = __activemask();
            unsigned bal = __ballot_sync(amask, take);
            if (take) {
                // all takers in this warp share the same seg (uniform per vec-range? not
                // across level boundary vecs in same warp — use match on seg for safety)
                unsigned mm = __match_any_sync(bal, seg);
                int leader = __ffs(mm) - 1;
                unsigned rank = __popc(mm & ((1u << (threadIdx.x & 31)) - 1u));
                unsigned basep = 0;
                if ((int)(threadIdx.x & 31) == leader)
                    basep = atomicAdd(&g_colcnt[seg], (unsigned)__popc(mm));
                basep = __shfl_sync(mm, basep, leader);
                unsigned idx = basep + rank;
                if (idx < CAP) {
                    g_colkey[(size_t)seg*CAP + idx] = key;
                    g_colpos[(size_t)seg*CAP + idx] = (unsigned)((e + j) - base);
                }
            }
        }
    }
}

// ---------------- block-level histogram select (descending) ----------------
__device__ __forceinline__ void bsel(unsigned* sh, int nb, unsigned target,
                                     int* r_bin, unsigned* r_krem)
{
    __shared__ unsigned gsum[64];
    int tid = threadIdx.x;
    int ngroups = nb / 32;
    if (tid < ngroups) {
        unsigned s = 0;
        for (int j = 0; j < 32; ++j) s += sh[tid*32 + j];
        gsum[tid] = s;
    }
    __syncthreads();
    if (tid == 0) {
        unsigned cum = 0;
        *r_bin = 0; *r_krem = target;
        for (int g = ngroups - 1; g >= 0; --g) {
            if (cum + gsum[g] >= target) {
                for (int b = g*32 + 31; b >= g*32; --b) {
                    if (cum + sh[b] >= target) { *r_bin = b; *r_krem = target - cum; return; }
                    cum += sh[b];
                }
            }
            cum += gsum[g];
        }
    }
}

// ---------------- seg_select: exact top-1000 within collected list + decode ------------
__global__ void seg_select_kernel(const float* __restrict__ r0, const float* __restrict__ r1,
                                  const float* __restrict__ r2, const float* __restrict__ l0,
                                  const float* __restrict__ l1, const float* __restrict__ l2)
{
    __shared__ unsigned sh[2048];
    __shared__ int s_bin; __shared__ unsigned s_krem;
    __shared__ unsigned s_T, s_allow, s_emit, s_tie;
    int seg = blockIdx.x;
    int n = seg / 3, lev = seg % 3;
    unsigned mraw = g_colcnt[seg];
    int m = (int)(mraw < CAP ? mraw : CAP);
    const unsigned* keys = g_colkey + (size_t)seg*CAP;
    const unsigned* poss = g_colpos + (size_t)seg*CAP;
    int tid = threadIdx.x;

    if (tid == 0) { s_emit = 0; s_tie = 0; }

    if (m <= KSEL) {
        if (tid == 0) { s_T = 0; s_allow = 0; }
        __syncthreads();
    } else {
        for (int i = tid; i < 2048; i += blockDim.x) sh[i] = 0;
        __syncthreads();
        for (int i = tid; i < m; i += blockDim.x)
            atomicAdd(&sh[keys[i] >> 21], 1u);
        __syncthreads();
        bsel(sh, 2048, KSEL, &s_bin, &s_krem);
        __syncthreads();
        unsigned b1 = (unsigned)s_bin, want = s_krem;
        __syncthreads();
        for (int i = tid; i < 2048; i += blockDim.x) sh[i] = 0;
        __syncthreads();
        for (int i = tid; i < m; i += blockDim.x) {
            unsigned key = keys[i];
            if ((key >> 21) == b1) atomicAdd(&sh[(key >> 10) & 0x7FF], 1u);
        }
        __syncthreads();
        bsel(sh, 2048, want, &s_bin, &s_krem);
        __syncthreads();
        unsigned b2 = (unsigned)s_bin; want = s_krem;
        unsigned pfx2 = (b1 << 11) | b2;
        __syncthreads();
        for (int i = tid; i < 1024; i += blockDim.x) sh[i] = 0;
        __syncthreads();
        for (int i = tid; i < m; i += blockDim.x) {
            unsigned key = keys[i];
            if ((key >> 10) == pfx2) atomicAdd(&sh[key & 0x3FF], 1u);
        }
        __syncthreads();
        bsel(sh, 1024, want, &s_bin, &s_krem);
        __syncthreads();
        if (tid == 0) { s_T = (pfx2 << 10) | (unsigned)s_bin; s_allow = s_krem; }
        __syncthreads();
    }
    unsigned T = s_T, allow = s_allow;

    const float* rg; const float* lc; int HW; float sf;
    if (lev == 0)      { rg = r0 + (size_t)n*40000; lc = l0; HW = 10000; sf = 8.0f; }
    else if (lev == 1) { rg = r1 + (size_t)n*10000; lc = l1; HW = 2500;  sf = 16.0f; }
    else               { rg = r2 + (size_t)n*2500;  lc = l2; HW = 625;   sf = 32.0f; }

    for (int i = tid; i < m; i += blockDim.x) {
        unsigned key = keys[i];
        bool take;
        if (m <= KSEL) take = true;
        else {
            take = key > T;
            if (!take && key == T && allow) take = (atomicAdd(&s_tie, 1u) < allow);
        }
        if (!take) continue;
        unsigned slot = atomicAdd(&s_emit, 1u);
        unsigned pos = poss[i];
        int c = (int)pos / HW, hw = (int)pos - c * HW;
        float l = rg[hw]        * sf;
        float t = rg[HW + hw]   * sf;
        float r = rg[2*HW + hw] * sf;
        float b = rg[3*HW + hw] * sf;
        float x = lc[2*hw], y = lc[2*hw + 1];
        float x1 = fminf(fmaxf(x - l, 0.f), 800.f);
        float y1 = fminf(fmaxf(y - t, 0.f), 800.f);
        float x2 = fminf(fmaxf(x + r, 0.f), 800.f);
        float y2 = fminf(fmaxf(y + b, 0.f), 800.f);
        int g = n * NCAND + lev * KSEL + (int)slot;
        g_cbox[g] = make_float4(x1, y1, x2, y2);
        g_csc[g]  = sqrtf(__uint_as_float(key));
        g_ccls[g] = c + 1;
    }
}

// ---------------- greedy NMS (one block per image) ----------------
__global__ __launch_bounds__(1024) void nms_kernel(float* __restrict__ out)
{
    extern __shared__ unsigned char smraw[];
    float* ox1 = (float*)smraw;
    float* oy1 = ox1 + NCAND;
    float* ox2 = oy1 + NCAND;
    float* oy2 = ox2 + NCAND;
    float* oar = oy2 + NCAND;
    float* osc = oar + NCAND;
    int*   ocl = (int*)(osc + NCAND);

    __shared__ float rs[32]; __shared__ int ri[32];
    __shared__ float sB; __shared__ int sI;

    int n = blockIdx.x;
    int tid = threadIdx.x;
    int lane = tid & 31, wid = tid >> 5;

    for (int i = tid; i < NCAND; i += blockDim.x) {
        float s = g_csc[n*NCAND + i];
        float4 b = g_cbox[n*NCAND + i];
        int c = g_ccls[n*NCAND + i];
        float x1, y1, x2, y2, a;
        if (s > 0.f) {
            float off = (float)c * 4096.0f;
            x1 = b.x + off; y1 = b.y + off; x2 = b.z + off; y2 = b.w + off;
            a = (x2 - x1) * (y2 - y1);
        } else {
            s = -1.0f; x1 = y1 = x2 = y2 = a = 0.f;
        }
        ox1[i] = x1; oy1[i] = y1; ox2[i] = x2; oy2[i] = y2;
        oar[i] = a;  osc[i] = s;  ocl[i] = c;
    }
    __syncthreads();

    for (int it = 0; it < NPICK; ++it) {
        float bs = -2.0f; int bi = NCAND;
        for (int i = tid; i < NCAND; i += blockDim.x) {
            float s = osc[i];
            if (s > bs || (s == bs && i < bi)) { bs = s; bi = i; }
        }
        #pragma unroll
        for (int o = 16; o; o >>= 1) {
            float s2 = __shfl_down_sync(0xFFFFFFFFu, bs, o);
            int   i2 = __shfl_down_sync(0xFFFFFFFFu, bi, o);
            if (s2 > bs || (s2 == bs && i2 < bi)) { bs = s2; bi = i2; }
        }
        if (lane == 0) { rs[wid] = bs; ri[wid] = bi; }
        __syncthreads();
        if (wid == 0) {
            float s = rs[lane]; int b = ri[lane];
            #pragma unroll
            for (int o = 16; o; o >>= 1) {
                float s2 = __shfl_down_sync(0xFFFFFFFFu, s, o);
                int   b2 = __shfl_down_sync(0xFFFFFFFFu, b, o);
                if (s2 > s || (s2 == s && b2 < b)) { s = s2; b = b2; }
            }
            if (lane == 0) { sB = s; sI = b; }
        }
        __syncthreads();
        bs = sB; bi = sI;
        bool keep = bs > 0.0f;

        if (tid < 7) {
            int row = n * NPICK + it;
            if (tid < 4)       out[OFS_BOX + row*4 + tid] = keep ? ((const float*)&g_cbox[n*NCAND + bi])[tid] : 0.f;
            else if (tid == 4) out[OFS_SC + row] = keep ? bs : 0.f;
            else if (tid == 5) out[OFS_CL + row] = keep ? (float)ocl[bi] : 0.f;
            else               out[OFS_KP + row] = keep ? 1.0f : 0.f;
        }

        float px1 = ox1[bi], py1 = oy1[bi], px2 = ox2[bi], py2 = oy2[bi], pa = oar[bi];
        for (int i = tid; i < NCAND; i += blockDim.x) {
            if (i == bi) { osc[i] = -1.0f; continue; }
            float xx1 = fmaxf(px1, ox1[i]);
            float yy1 = fmaxf(py1, oy1[i]);
            float xx2 = fminf(px2, ox2[i]);
            float yy2 = fminf(py2, oy2[i]);
            float inter = fmaxf(xx2 - xx1, 0.f) * fmaxf(yy2 - yy1, 0.f);
            float iou = inter / (oar[i] + pa - inter + 1e-9f);
            if (iou > 0.6f) osc[i] = -1.0f;
        }
        __syncthreads();
    }
}

// ---------------- launch ----------------
extern "C" void kernel_launch(void* const* d_in, const int* in_sizes, int n_in,
                              void* d_out, int out_size)
{
    const float *loc0, *loc1, *loc2, *cls0, *cls1, *cls2;
    const float *reg0, *reg1, *reg2, *ctr0, *ctr1, *ctr2;
    if (in_sizes[1] == 16 * 80 * 10000) {
        // dict order: per-level (loc, cls, reg, ctr)
        loc0 = (const float*)d_in[0];  cls0 = (const float*)d_in[1];
        reg0 = (const float*)d_in[2];  ctr0 = (const float*)d_in[3];
        loc1 = (const float*)d_in[4];  cls1 = (const float*)d_in[5];
        reg1 = (const float*)d_in[6];  ctr1 = (const float*)d_in[7];
        loc2 = (const float*)d_in[8];  cls2 = (const float*)d_in[9];
        reg2 = (const float*)d_in[10]; ctr2 = (const float*)d_in[11];
    } else {
        loc0 = (const float*)d_in[0];  loc1 = (const float*)d_in[1];  loc2 = (const float*)d_in[2];
        cls0 = (const float*)d_in[3];  cls1 = (const float*)d_in[4];  cls2 = (const float*)d_in[5];
        reg0 = (const float*)d_in[6];  reg1 = (const float*)d_in[7];  reg2 = (const float*)d_in[8];
        ctr0 = (const float*)d_in[9];  ctr1 = (const float*)d_in[10]; ctr2 = (const float*)d_in[11];
    }
    float* out = (float*)d_out;

    cudaFuncSetAttribute(nms_kernel, cudaFuncAttributeMaxDynamicSharedMemorySize, 7 * NCAND * 4);

    init_kernel<<<416, 256>>>(ctr0, ctr1, ctr2);
    pass1_kernel<<<dim3(64, NIMG), 256>>>(cls0, cls1, cls2);
    select1_kernel<<<NIMG*3, 256>>>();
    collect_kernel<<<dim3(64, NIMG), 256>>>(cls0, cls1, cls2);
    seg_select_kernel<<<NIMG*3, 256>>>(reg0, reg1, reg2, loc0, loc1, loc2);
    nms_kernel<<<NIMG, 1024, 7 * NCAND * 4>>>(out);
}

// round 5
// speedup vs baseline: 2.2859x; 1.1334x over previous
#include <cuda_runtime.h>
#include <math.h>

#define NIMG   16
#define NCLS   80
#define KSEL   1000
#define NCAND  3000
#define NPICK  100
#define MTOT   1050000
#define NVEC   (MTOT/4)
#define CAP    262144

// fine histogram: bin 0 = underflow, then 17 exponents x 512 mantissa bins
#define EMIN   110
#define NEXP   17
#define NMAN   512
#define NBIN   (1 + NEXP*NMAN)     // 8705

// Output layout (float32, concatenated tuple: boxes, scores, classes, keep)
#define OFS_BOX 0
#define OFS_SC  (NIMG*NPICK*4)
#define OFS_CL  (OFS_SC + NIMG*NPICK)
#define OFS_KP  (OFS_CL + NIMG*NPICK)

// ---------------- scratch (device globals, no allocation) ----------------
__device__ unsigned g_h1[NIMG*3*NBIN];
__device__ unsigned g_F[NIMG*3];
__device__ unsigned g_colcnt[NIMG*3];
__device__ unsigned g_colkey[(size_t)NIMG*3*CAP];
__device__ unsigned g_colpos[(size_t)NIMG*3*CAP];
__device__ float4   g_cbox[NIMG*NCAND];
__device__ float    g_csc[NIMG*NCAND];
__device__ int      g_ccls[NIMG*NCAND];

__device__ __forceinline__ float fsigm(float x)
{
    return __fdividef(1.0f, 1.0f + __expf(-x));
}

__device__ __forceinline__ unsigned keybin(unsigned key)
{
    unsigned exp = key >> 23;
    if (exp < EMIN) return 0u;
    return 1u + ((exp - EMIN) << 9) + ((key >> 14) & (NMAN - 1));
}

// ---------------- init: zero hists/counters, invalidate candidates ----------------
__global__ void init_kernel()
{
    int i0 = blockIdx.x * blockDim.x + threadIdx.x;
    int st = gridDim.x * blockDim.x;
    for (int j = i0; j < NIMG*3*NBIN; j += st) g_h1[j] = 0;
    for (int j = i0; j < NIMG*3; j += st) g_colcnt[j] = 0;
    for (int j = i0; j < NIMG*NCAND; j += st) {
        g_csc[j] = -1.0f; g_ccls[j] = 0;
        g_cbox[j] = make_float4(0.f, 0.f, 0.f, 0.f);
    }
}

// ---------------- per-vec key computation ----------------
// VEC=true: HW divisible by 4 -> ctr vector load (hw..hw+3 same row)
template<int HW, bool VEC>
__device__ __forceinline__ void keys4(int el, const float* __restrict__ src,
                                      const float* __restrict__ ctr, unsigned k4[4])
{
    float4 v = *reinterpret_cast<const float4*>(src + el);
    float vv[4] = {v.x, v.y, v.z, v.w};
    float tt[4];
    if (VEC) {
        int c = el / HW;
        int hw = el - c * HW;
        float4 tv = *reinterpret_cast<const float4*>(ctr + hw);
        tt[0] = fsigm(tv.x); tt[1] = fsigm(tv.y); tt[2] = fsigm(tv.z); tt[3] = fsigm(tv.w);
    } else {
        #pragma unroll
        for (int j = 0; j < 4; ++j) {
            int e = el + j;
            int c = e / HW;
            tt[j] = fsigm(ctr[e - c * HW]);
        }
    }
    #pragma unroll
    for (int j = 0; j < 4; ++j) {
        float s = fsigm(vv[j]);
        k4[j] = (s > 0.05f) ? __float_as_uint(s * tt[j]) : 0u;
    }
}

// ---------------- pass 1: fused score -> fine histogram (level-partitioned blocks) ------
// blockIdx.x in [0,48): level0 ; [48,60): level1 ; [60,64): level2
__global__ __launch_bounds__(256) void pass1_kernel(
    const float* __restrict__ c0, const float* __restrict__ c1, const float* __restrict__ c2,
    const float* __restrict__ t0, const float* __restrict__ t1, const float* __restrict__ t2)
{
    __shared__ unsigned sh[NBIN];
    for (int i = threadIdx.x; i < NBIN; i += blockDim.x) sh[i] = 0;
    __syncthreads();

    int n = blockIdx.y;
    int bx = blockIdx.x;
    int lev, b0, nb, vlo, vhi;
    const float* src; const float* ctr;
    if (bx < 48)      { lev = 0; b0 = 0;  nb = 48; vlo = 0;      vhi = 200000;
                        src = c0 + (size_t)n*800000; ctr = t0 + (size_t)n*10000; }
    else if (bx < 60) { lev = 1; b0 = 48; nb = 12; vlo = 200000; vhi = 250000;
                        src = c1 + (size_t)n*200000; ctr = t1 + (size_t)n*2500; }
    else              { lev = 2; b0 = 60; nb = 4;  vlo = 250000; vhi = 262500;
                        src = c2 + (size_t)n*50000;  ctr = t2 + (size_t)n*625; }
    int vstride = nb * blockDim.x;
    int vstart = vlo + (bx - b0) * blockDim.x + threadIdx.x;
    int base = vlo * 4;

    for (int v = vstart; v < vhi; v += vstride) {
        int e = v * 4 - base;
        unsigned k4[4];
        if (lev == 0)      keys4<10000, true>(e, src, ctr, k4);
        else if (lev == 1) keys4<2500, true>(e, src, ctr, k4);
        else               keys4<625, false>(e, src, ctr, k4);
        #pragma unroll
        for (int j = 0; j < 4; ++j)
            if (k4[j]) atomicAdd(&sh[keybin(k4[j])], 1u);
    }
    __syncthreads();
    unsigned* gh = g_h1 + (n*3 + lev) * NBIN;
    for (int i = threadIdx.x; i < NBIN; i += blockDim.x)
        if (sh[i]) atomicAdd(&gh[i], sh[i]);
}

// ---------------- select1: per-segment key floor F of the 1000th key ----------------
__global__ void select1_kernel()
{
    __shared__ unsigned csum[(NBIN + 31) / 32];
    const int NCH = (NBIN + 31) / 32;
    int seg = blockIdx.x;
    int tid = threadIdx.x;
    const unsigned* gh = g_h1 + (size_t)seg * NBIN;
    for (int ch = tid; ch < NCH; ch += blockDim.x) {
        unsigned s = 0;
        int hi = min(NBIN, (ch + 1) * 32);
        for (int b = ch * 32; b < hi; ++b) s += gh[b];
        csum[ch] = s;
    }
    __syncthreads();
    if (tid == 0) {
        unsigned cum = 0;
        unsigned F = 1;
        for (int ch = NCH - 1; ch >= 0; --ch) {
            if (cum + csum[ch] >= KSEL) {
                int hi = min(NBIN, (ch + 1) * 32);
                for (int b = hi - 1; b >= ch * 32; --b) {
                    cum += gh[b];
                    if (cum >= KSEL) {
                        if (b == 0) F = 1;
                        else {
                            unsigned bb = (unsigned)b - 1;
                            unsigned exp = EMIN + (bb >> 9);
                            unsigned man = bb & (NMAN - 1);
                            F = (exp << 23) | (man << 14);
                            if (F == 0) F = 1;
                        }
                        break;
                    }
                }
                break;
            }
            cum += csum[ch];
        }
        g_F[seg] = F;   // F=1 if total < KSEL (collect everything nonzero)
    }
}

// ---------------- collect: recompute keys, append (key,pos) with key >= F --------------
__global__ __launch_bounds__(256) void collect_kernel(
    const float* __restrict__ c0, const float* __restrict__ c1, const float* __restrict__ c2,
    const float* __restrict__ t0, const float* __restrict__ t1, const float* __restrict__ t2)
{
    int n = blockIdx.y;
    int bx = blockIdx.x;
    int lev, b0, nb, vlo, vhi;
    const float* src; const float* ctr;
    if (bx < 48)      { lev = 0; b0 = 0;  nb = 48; vlo = 0;      vhi = 200000;
                        src = c0 + (size_t)n*800000; ctr = t0 + (size_t)n*10000; }
    else if (bx < 60) { lev = 1; b0 = 48; nb = 12; vlo = 200000; vhi = 250000;
                        src = c1 + (size_t)n*200000; ctr = t1 + (size_t)n*2500; }
    else              { lev = 2; b0 = 60; nb = 4;  vlo = 250000; vhi = 262500;
                        src = c2 + (size_t)n*50000;  ctr = t2 + (size_t)n*625; }
    int seg = n*3 + lev;
    unsigned F = g_F[seg];
    int vstride = nb * blockDim.x;
    int vstart = vlo + (bx - b0) * blockDim.x + threadIdx.x;
    int base = vlo * 4;
    int lane = threadIdx.x & 31;

    for (int v = vstart; v < vhi; v += vstride) {
        int e = v * 4 - base;
        unsigned k4[4];
        if (lev == 0)      keys4<10000, true>(e, src, ctr, k4);
        else if (lev == 1) keys4<2500, true>(e, src, ctr, k4);
        else               keys4<625, false>(e, src, ctr, k4);
        #pragma unroll
        for (int j = 0; j < 4; ++j) {
            unsigned key = k4[j];
            bool take = key >= F;                // F >= 1 so key==0 never taken
            unsigned amask = __activemask();
            unsigned bal = __ballot_sync(amask, take);
            if (take) {
                int leader = __ffs(bal) - 1;
                unsigned rank = __popc(bal & ((1u << lane) - 1u));
                unsigned basep = 0;
                if (lane == leader)
                    basep = atomicAdd(&g_colcnt[seg], (unsigned)__popc(bal));
                basep = __shfl_sync(bal, basep, leader);
                unsigned idx = basep + rank;
                if (idx < CAP) {
                    g_colkey[(size_t)seg*CAP + idx] = key;
                    g_colpos[(size_t)seg*CAP + idx] = (unsigned)(e + j);
                }
            }
        }
    }
}

// ---------------- block-level histogram select (descending) ----------------
__device__ __forceinline__ void bsel(unsigned* sh, int nb, unsigned target,
                                     int* r_bin, unsigned* r_krem)
{
    __shared__ unsigned gsum[64];
    int tid = threadIdx.x;
    int ngroups = nb / 32;
    if (tid < ngroups) {
        unsigned s = 0;
        for (int j = 0; j < 32; ++j) s += sh[tid*32 + j];
        gsum[tid] = s;
    }
    __syncthreads();
    if (tid == 0) {
        unsigned cum = 0;
        *r_bin = 0; *r_krem = target;
        for (int g = ngroups - 1; g >= 0; --g) {
            if (cum + gsum[g] >= target) {
                for (int b = g*32 + 31; b >= g*32; --b) {
                    if (cum + sh[b] >= target) { *r_bin = b; *r_krem = target - cum; return; }
                    cum += sh[b];
                }
            }
            cum += gsum[g];
        }
    }
}

// ---------------- seg_select: exact top-1000 within collected list + decode ------------
__global__ void seg_select_kernel(const float* __restrict__ r0, const float* __restrict__ r1,
                                  const float* __restrict__ r2, const float* __restrict__ l0,
                                  const float* __restrict__ l1, const float* __restrict__ l2)
{
    __shared__ unsigned sh[2048];
    __shared__ int s_bin; __shared__ unsigned s_krem;
    __shared__ unsigned s_T, s_allow, s_emit, s_tie;
    int seg = blockIdx.x;
    int n = seg / 3, lev = seg % 3;
    unsigned mraw = g_colcnt[seg];
    int m = (int)(mraw < CAP ? mraw : CAP);
    const unsigned* keys = g_colkey + (size_t)seg*CAP;
    const unsigned* poss = g_colpos + (size_t)seg*CAP;
    int tid = threadIdx.x;

    if (tid == 0) { s_emit = 0; s_tie = 0; }

    if (m <= KSEL) {
        if (tid == 0) { s_T = 0; s_allow = 0; }
        __syncthreads();
    } else {
        for (int i = tid; i < 2048; i += blockDim.x) sh[i] = 0;
        __syncthreads();
        for (int i = tid; i < m; i += blockDim.x)
            atomicAdd(&sh[keys[i] >> 21], 1u);
        __syncthreads();
        bsel(sh, 2048, KSEL, &s_bin, &s_krem);
        __syncthreads();
        unsigned b1 = (unsigned)s_bin, want = s_krem;
        __syncthreads();
        for (int i = tid; i < 2048; i += blockDim.x) sh[i] = 0;
        __syncthreads();
        for (int i = tid; i < m; i += blockDim.x) {
            unsigned key = keys[i];
            if ((key >> 21) == b1) atomicAdd(&sh[(key >> 10) & 0x7FF], 1u);
        }
        __syncthreads();
        bsel(sh, 2048, want, &s_bin, &s_krem);
        __syncthreads();
        unsigned b2 = (unsigned)s_bin; want = s_krem;
        unsigned pfx2 = (b1 << 11) | b2;
        __syncthreads();
        for (int i = tid; i < 1024; i += blockDim.x) sh[i] = 0;
        __syncthreads();
        for (int i = tid; i < m; i += blockDim.x) {
            unsigned key = keys[i];
            if ((key >> 10) == pfx2) atomicAdd(&sh[key & 0x3FF], 1u);
        }
        __syncthreads();
        bsel(sh, 1024, want, &s_bin, &s_krem);
        __syncthreads();
        if (tid == 0) { s_T = (pfx2 << 10) | (unsigned)s_bin; s_allow = s_krem; }
        __syncthreads();
    }
    unsigned T = s_T, allow = s_allow;

    const float* rg; const float* lc; int HW; float sf;
    if (lev == 0)      { rg = r0 + (size_t)n*40000; lc = l0; HW = 10000; sf = 8.0f; }
    else if (lev == 1) { rg = r1 + (size_t)n*10000; lc = l1; HW = 2500;  sf = 16.0f; }
    else               { rg = r2 + (size_t)n*2500;  lc = l2; HW = 625;   sf = 32.0f; }

    for (int i = tid; i < m; i += blockDim.x) {
        unsigned key = keys[i];
        bool take;
        if (m <= KSEL) take = true;
        else {
            take = key > T;
            if (!take && key == T && allow) take = (atomicAdd(&s_tie, 1u) < allow);
        }
        if (!take) continue;
        unsigned slot = atomicAdd(&s_emit, 1u);
        unsigned pos = poss[i];
        int c = (int)pos / HW, hw = (int)pos - c * HW;
        float l = rg[hw]        * sf;
        float t = rg[HW + hw]   * sf;
        float r = rg[2*HW + hw] * sf;
        float b = rg[3*HW + hw] * sf;
        float x = lc[2*hw], y = lc[2*hw + 1];
        float x1 = fminf(fmaxf(x - l, 0.f), 800.f);
        float y1 = fminf(fmaxf(y - t, 0.f), 800.f);
        float x2 = fminf(fmaxf(x + r, 0.f), 800.f);
        float y2 = fminf(fmaxf(y + b, 0.f), 800.f);
        int g = n * NCAND + lev * KSEL + (int)slot;
        g_cbox[g] = make_float4(x1, y1, x2, y2);
        g_csc[g]  = sqrtf(__uint_as_float(key));
        g_ccls[g] = c + 1;
    }
}

// ---------------- greedy NMS (one block per image) ----------------
__global__ __launch_bounds__(1024) void nms_kernel(float* __restrict__ out)
{
    extern __shared__ unsigned char smraw[];
    float* ox1 = (float*)smraw;
    float* oy1 = ox1 + NCAND;
    float* ox2 = oy1 + NCAND;
    float* oy2 = ox2 + NCAND;
    float* oar = oy2 + NCAND;
    float* osc = oar + NCAND;
    int*   ocl = (int*)(osc + NCAND);

    __shared__ float rs[32]; __shared__ int ri[32];
    __shared__ float sB; __shared__ int sI;

    int n = blockIdx.x;
    int tid = threadIdx.x;
    int lane = tid & 31, wid = tid >> 5;

    for (int i = tid; i < NCAND; i += blockDim.x) {
        float s = g_csc[n*NCAND + i];
        float4 b = g_cbox[n*NCAND + i];
        int c = g_ccls[n*NCAND + i];
        float x1, y1, x2, y2, a;
        if (s > 0.f) {
            float off = (float)c * 4096.0f;
            x1 = b.x + off; y1 = b.y + off; x2 = b.z + off; y2 = b.w + off;
            a = (x2 - x1) * (y2 - y1);
        } else {
            s = -1.0f; x1 = y1 = x2 = y2 = a = 0.f;
        }
        ox1[i] = x1; oy1[i] = y1; ox2[i] = x2; oy2[i] = y2;
        oar[i] = a;  osc[i] = s;  ocl[i] = c;
    }
    __syncthreads();

    for (int it = 0; it < NPICK; ++it) {
        float bs = -2.0f; int bi = NCAND;
        for (int i = tid; i < NCAND; i += blockDim.x) {
            float s = osc[i];
            if (s > bs || (s == bs && i < bi)) { bs = s; bi = i; }
        }
        #pragma unroll
        for (int o = 16; o; o >>= 1) {
            float s2 = __shfl_down_sync(0xFFFFFFFFu, bs, o);
            int   i2 = __shfl_down_sync(0xFFFFFFFFu, bi, o);
            if (s2 > bs || (s2 == bs && i2 < bi)) { bs = s2; bi = i2; }
        }
        if (lane == 0) { rs[wid] = bs; ri[wid] = bi; }
        __syncthreads();
        if (wid == 0) {
            float s = rs[lane]; int b = ri[lane];
            #pragma unroll
            for (int o = 16; o; o >>= 1) {
                float s2 = __shfl_down_sync(0xFFFFFFFFu, s, o);
                int   b2 = __shfl_down_sync(0xFFFFFFFFu, b, o);
                if (s2 > s || (s2 == s && b2 < b)) { s = s2; b = b2; }
            }
            if (lane == 0) { sB = s; sI = b; }
        }
        __syncthreads();
        bs = sB; bi = sI;
        bool keep = bs > 0.0f;

        if (tid < 7) {
            int row = n * NPICK + it;
            if (tid < 4)       out[OFS_BOX + row*4 + tid] = keep ? ((const float*)&g_cbox[n*NCAND + bi])[tid] : 0.f;
            else if (tid == 4) out[OFS_SC + row] = keep ? bs : 0.f;
            else if (tid == 5) out[OFS_CL + row] = keep ? (float)ocl[bi] : 0.f;
            else               out[OFS_KP + row] = keep ? 1.0f : 0.f;
        }

        float px1 = ox1[bi], py1 = oy1[bi], px2 = ox2[bi], py2 = oy2[bi], pa = oar[bi];
        for (int i = tid; i < NCAND; i += blockDim.x) {
            if (i == bi) { osc[i] = -1.0f; continue; }
            float xx1 = fmaxf(px1, ox1[i]);
            float yy1 = fmaxf(py1, oy1[i]);
            float xx2 = fminf(px2, ox2[i]);
            float yy2 = fminf(py2, oy2[i]);
            float inter = fmaxf(xx2 - xx1, 0.f) * fmaxf(yy2 - yy1, 0.f);
            float iou = inter / (oar[i] + pa - inter + 1e-9f);
            if (iou > 0.6f) osc[i] = -1.0f;
        }
        __syncthreads();
    }
}

// ---------------- launch ----------------
extern "C" void kernel_launch(void* const* d_in, const int* in_sizes, int n_in,
                              void* d_out, int out_size)
{
    const float *loc0, *loc1, *loc2, *cls0, *cls1, *cls2;
    const float *reg0, *reg1, *reg2, *ctr0, *ctr1, *ctr2;
    if (in_sizes[1] == 16 * 80 * 10000) {
        // dict order: per-level (loc, cls, reg, ctr)
        loc0 = (const float*)d_in[0];  cls0 = (const float*)d_in[1];
        reg0 = (const float*)d_in[2];  ctr0 = (const float*)d_in[3];
        loc1 = (const float*)d_in[4];  cls1 = (const float*)d_in[5];
        reg1 = (const float*)d_in[6];  ctr1 = (const float*)d_in[7];
        loc2 = (const float*)d_in[8];  cls2 = (const float*)d_in[9];
        reg2 = (const float*)d_in[10]; ctr2 = (const float*)d_in[11];
    } else {
        loc0 = (const float*)d_in[0];  loc1 = (const float*)d_in[1];  loc2 = (const float*)d_in[2];
        cls0 = (const float*)d_in[3];  cls1 = (const float*)d_in[4];  cls2 = (const float*)d_in[5];
        reg0 = (const float*)d_in[6];  reg1 = (const float*)d_in[7];  reg2 = (const float*)d_in[8];
        ctr0 = (const float*)d_in[9];  ctr1 = (const float*)d_in[10]; ctr2 = (const float*)d_in[11];
    }
    float* out = (float*)d_out;

    cudaFuncSetAttribute(nms_kernel, cudaFuncAttributeMaxDynamicSharedMemorySize, 7 * NCAND * 4);

    init_kernel<<<416, 256>>>();
    pass1_kernel<<<dim3(64, NIMG), 256>>>(cls0, cls1, cls2, ctr0, ctr1, ctr2);
    select1_kernel<<<NIMG*3, 256>>>();
    collect_kernel<<<dim3(64, NIMG), 256>>>(cls0, cls1, cls2, ctr0, ctr1, ctr2);
    seg_select_kernel<<<NIMG*3, 256>>>(reg0, reg1, reg2, loc0, loc1, loc2);
    nms_kernel<<<NIMG, 1024, 7 * NCAND * 4>>>(out);
}

// round 6
// speedup vs baseline: 2.2990x; 1.0057x over previous
#include <cuda_runtime.h>
#include <math.h>

#define NIMG   16
#define NCLS   80
#define KSEL   1000
#define NCAND  3000
#define NPICK  100
#define MTOT   1050000
#define NVEC   (MTOT/4)
#define CAP    262144

// fine histogram: bin 0 = underflow, then 17 exponents x 512 mantissa bins
#define EMIN   110
#define NEXP   17
#define NMAN   512
#define NBIN   (1 + NEXP*NMAN)     // 8705

// Output layout (float32, concatenated tuple: boxes, scores, classes, keep)
#define OFS_BOX 0
#define OFS_SC  (NIMG*NPICK*4)
#define OFS_CL  (OFS_SC + NIMG*NPICK)
#define OFS_KP  (OFS_CL + NIMG*NPICK)

// ---------------- scratch (device globals, no allocation) ----------------
__device__ unsigned g_h1[NIMG*3*NBIN];
__device__ unsigned g_F[NIMG*3];
__device__ unsigned g_colcnt[NIMG*3];
__device__ unsigned g_colkey[(size_t)NIMG*3*CAP];
__device__ unsigned g_colpos[(size_t)NIMG*3*CAP];
__device__ float4   g_cbox[NIMG*NCAND];
__device__ float    g_csc[NIMG*NCAND];
__device__ int      g_ccls[NIMG*NCAND];

__device__ __forceinline__ float fsigm(float x)
{
    return __fdividef(1.0f, 1.0f + __expf(-x));
}

__device__ __forceinline__ unsigned keybin(unsigned key)
{
    unsigned exp = key >> 23;
    if (exp < EMIN) return 0u;
    return 1u + ((exp - EMIN) << 9) + ((key >> 14) & (NMAN - 1));
}

// ---------------- init: zero hists/counters, invalidate candidates ----------------
__global__ void init_kernel()
{
    int i0 = blockIdx.x * blockDim.x + threadIdx.x;
    int st = gridDim.x * blockDim.x;
    for (int j = i0; j < NIMG*3*NBIN; j += st) g_h1[j] = 0;
    for (int j = i0; j < NIMG*3; j += st) g_colcnt[j] = 0;
    for (int j = i0; j < NIMG*NCAND; j += st) {
        g_csc[j] = -1.0f; g_ccls[j] = 0;
        g_cbox[j] = make_float4(0.f, 0.f, 0.f, 0.f);
    }
}

// ---------------- per-vec key computation ----------------
// VEC=true: HW divisible by 4 -> ctr vector load (hw..hw+3 same row)
template<int HW, bool VEC>
__device__ __forceinline__ void keys4(int el, const float* __restrict__ src,
                                      const float* __restrict__ ctr, unsigned k4[4])
{
    float4 v = *reinterpret_cast<const float4*>(src + el);
    float vv[4] = {v.x, v.y, v.z, v.w};
    float tt[4];
    if (VEC) {
        int c = el / HW;
        int hw = el - c * HW;
        float4 tv = *reinterpret_cast<const float4*>(ctr + hw);
        tt[0] = fsigm(tv.x); tt[1] = fsigm(tv.y); tt[2] = fsigm(tv.z); tt[3] = fsigm(tv.w);
    } else {
        #pragma unroll
        for (int j = 0; j < 4; ++j) {
            int e = el + j;
            int c = e / HW;
            tt[j] = fsigm(ctr[e - c * HW]);
        }
    }
    #pragma unroll
    for (int j = 0; j < 4; ++j) {
        float s = fsigm(vv[j]);
        k4[j] = (s > 0.05f) ? __float_as_uint(s * tt[j]) : 0u;
    }
}

// ---------------- pass 1: fused score -> fine histogram (level-partitioned blocks) ------
// blockIdx.x in [0,48): level0 ; [48,60): level1 ; [60,64): level2
__global__ __launch_bounds__(256) void pass1_kernel(
    const float* __restrict__ c0, const float* __restrict__ c1, const float* __restrict__ c2,
    const float* __restrict__ t0, const float* __restrict__ t1, const float* __restrict__ t2)
{
    __shared__ unsigned sh[NBIN];
    for (int i = threadIdx.x; i < NBIN; i += blockDim.x) sh[i] = 0;
    __syncthreads();

    int n = blockIdx.y;
    int bx = blockIdx.x;
    int lev, b0, nb, vlo, vhi;
    const float* src; const float* ctr;
    if (bx < 48)      { lev = 0; b0 = 0;  nb = 48; vlo = 0;      vhi = 200000;
                        src = c0 + (size_t)n*800000; ctr = t0 + (size_t)n*10000; }
    else if (bx < 60) { lev = 1; b0 = 48; nb = 12; vlo = 200000; vhi = 250000;
                        src = c1 + (size_t)n*200000; ctr = t1 + (size_t)n*2500; }
    else              { lev = 2; b0 = 60; nb = 4;  vlo = 250000; vhi = 262500;
                        src = c2 + (size_t)n*50000;  ctr = t2 + (size_t)n*625; }
    int vstride = nb * blockDim.x;
    int vstart = vlo + (bx - b0) * blockDim.x + threadIdx.x;
    int base = vlo * 4;

    for (int v = vstart; v < vhi; v += vstride) {
        int e = v * 4 - base;
        unsigned k4[4];
        if (lev == 0)      keys4<10000, true>(e, src, ctr, k4);
        else if (lev == 1) keys4<2500, true>(e, src, ctr, k4);
        else               keys4<625, false>(e, src, ctr, k4);
        #pragma unroll
        for (int j = 0; j < 4; ++j)
            if (k4[j]) atomicAdd(&sh[keybin(k4[j])], 1u);
    }
    __syncthreads();
    unsigned* gh = g_h1 + (n*3 + lev) * NBIN;
    for (int i = threadIdx.x; i < NBIN; i += blockDim.x)
        if (sh[i]) atomicAdd(&gh[i], sh[i]);
}

// ---------------- select1: per-segment key floor F of the 1000th key ----------------
__global__ void select1_kernel()
{
    __shared__ unsigned csum[(NBIN + 31) / 32];
    const int NCH = (NBIN + 31) / 32;
    int seg = blockIdx.x;
    int tid = threadIdx.x;
    const unsigned* gh = g_h1 + (size_t)seg * NBIN;
    for (int ch = tid; ch < NCH; ch += blockDim.x) {
        unsigned s = 0;
        int hi = min(NBIN, (ch + 1) * 32);
        for (int b = ch * 32; b < hi; ++b) s += gh[b];
        csum[ch] = s;
    }
    __syncthreads();
    if (tid == 0) {
        unsigned cum = 0;
        unsigned F = 1;
        for (int ch = NCH - 1; ch >= 0; --ch) {
            if (cum + csum[ch] >= KSEL) {
                int hi = min(NBIN, (ch + 1) * 32);
                for (int b = hi - 1; b >= ch * 32; --b) {
                    cum += gh[b];
                    if (cum >= KSEL) {
                        if (b == 0) F = 1;
                        else {
                            unsigned bb = (unsigned)b - 1;
                            unsigned exp = EMIN + (bb >> 9);
                            unsigned man = bb & (NMAN - 1);
                            F = (exp << 23) | (man << 14);
                            if (F == 0) F = 1;
                        }
                        break;
                    }
                }
                break;
            }
            cum += csum[ch];
        }
        g_F[seg] = F;   // F=1 if total < KSEL (collect everything nonzero)
    }
}

// ---------------- collect: recompute keys, append (key,pos) with key >= F --------------
__global__ __launch_bounds__(256) void collect_kernel(
    const float* __restrict__ c0, const float* __restrict__ c1, const float* __restrict__ c2,
    const float* __restrict__ t0, const float* __restrict__ t1, const float* __restrict__ t2)
{
    int n = blockIdx.y;
    int bx = blockIdx.x;
    int lev, b0, nb, vlo, vhi;
    const float* src; const float* ctr;
    if (bx < 48)      { lev = 0; b0 = 0;  nb = 48; vlo = 0;      vhi = 200000;
                        src = c0 + (size_t)n*800000; ctr = t0 + (size_t)n*10000; }
    else if (bx < 60) { lev = 1; b0 = 48; nb = 12; vlo = 200000; vhi = 250000;
                        src = c1 + (size_t)n*200000; ctr = t1 + (size_t)n*2500; }
    else              { lev = 2; b0 = 60; nb = 4;  vlo = 250000; vhi = 262500;
                        src = c2 + (size_t)n*50000;  ctr = t2 + (size_t)n*625; }
    int seg = n*3 + lev;
    unsigned F = g_F[seg];
    int vstride = nb * blockDim.x;
    int vstart = vlo + (bx - b0) * blockDim.x + threadIdx.x;
    int base = vlo * 4;
    int lane = threadIdx.x & 31;

    for (int v = vstart; v < vhi; v += vstride) {
        int e = v * 4 - base;
        unsigned k4[4];
        if (lev == 0)      keys4<10000, true>(e, src, ctr, k4);
        else if (lev == 1) keys4<2500, true>(e, src, ctr, k4);
        else               keys4<625, false>(e, src, ctr, k4);
        #pragma unroll
        for (int j = 0; j < 4; ++j) {
            unsigned key = k4[j];
            bool take = key >= F;                // F >= 1 so key==0 never taken
            unsigned amask = __activemask();
            unsigned bal = __ballot_sync(amask, take);
            if (take) {
                int leader = __ffs(bal) - 1;
                unsigned rank = __popc(bal & ((1u << lane) - 1u));
                unsigned basep = 0;
                if (lane == leader)
                    basep = atomicAdd(&g_colcnt[seg], (unsigned)__popc(bal));
                basep = __shfl_sync(bal, basep, leader);
                unsigned idx = basep + rank;
                if (idx < CAP) {
                    g_colkey[(size_t)seg*CAP + idx] = key;
                    g_colpos[(size_t)seg*CAP + idx] = (unsigned)(e + j);
                }
            }
        }
    }
}

// ---------------- block-level histogram select (descending) ----------------
__device__ __forceinline__ void bsel(unsigned* sh, int nb, unsigned target,
                                     int* r_bin, unsigned* r_krem)
{
    __shared__ unsigned gsum[64];
    int tid = threadIdx.x;
    int ngroups = nb / 32;
    if (tid < ngroups) {
        unsigned s = 0;
        for (int j = 0; j < 32; ++j) s += sh[tid*32 + j];
        gsum[tid] = s;
    }
    __syncthreads();
    if (tid == 0) {
        unsigned cum = 0;
        *r_bin = 0; *r_krem = target;
        for (int g = ngroups - 1; g >= 0; --g) {
            if (cum + gsum[g] >= target) {
                for (int b = g*32 + 31; b >= g*32; --b) {
                    if (cum + sh[b] >= target) { *r_bin = b; *r_krem = target - cum; return; }
                    cum += sh[b];
                }
            }
            cum += gsum[g];
        }
    }
}

// ---------------- seg_select: exact top-1000 within collected list + decode ------------
__global__ void seg_select_kernel(const float* __restrict__ r0, const float* __restrict__ r1,
                                  const float* __restrict__ r2, const float* __restrict__ l0,
                                  const float* __restrict__ l1, const float* __restrict__ l2)
{
    __shared__ unsigned sh[2048];
    __shared__ int s_bin; __shared__ unsigned s_krem;
    __shared__ unsigned s_T, s_allow, s_emit, s_tie;
    int seg = blockIdx.x;
    int n = seg / 3, lev = seg % 3;
    unsigned mraw = g_colcnt[seg];
    int m = (int)(mraw < CAP ? mraw : CAP);
    const unsigned* keys = g_colkey + (size_t)seg*CAP;
    const unsigned* poss = g_colpos + (size_t)seg*CAP;
    int tid = threadIdx.x;

    if (tid == 0) { s_emit = 0; s_tie = 0; }

    if (m <= KSEL) {
        if (tid == 0) { s_T = 0; s_allow = 0; }
        __syncthreads();
    } else {
        for (int i = tid; i < 2048; i += blockDim.x) sh[i] = 0;
        __syncthreads();
        for (int i = tid; i < m; i += blockDim.x)
            atomicAdd(&sh[keys[i] >> 21], 1u);
        __syncthreads();
        bsel(sh, 2048, KSEL, &s_bin, &s_krem);
        __syncthreads();
        unsigned b1 = (unsigned)s_bin, want = s_krem;
        __syncthreads();
        for (int i = tid; i < 2048; i += blockDim.x) sh[i] = 0;
        __syncthreads();
        for (int i = tid; i < m; i += blockDim.x) {
            unsigned key = keys[i];
            if ((key >> 21) == b1) atomicAdd(&sh[(key >> 10) & 0x7FF], 1u);
        }
        __syncthreads();
        bsel(sh, 2048, want, &s_bin, &s_krem);
        __syncthreads();
        unsigned b2 = (unsigned)s_bin; want = s_krem;
        unsigned pfx2 = (b1 << 11) | b2;
        __syncthreads();
        for (int i = tid; i < 1024; i += blockDim.x) sh[i] = 0;
        __syncthreads();
        for (int i = tid; i < m; i += blockDim.x) {
            unsigned key = keys[i];
            if ((key >> 10) == pfx2) atomicAdd(&sh[key & 0x3FF], 1u);
        }
        __syncthreads();
        bsel(sh, 1024, want, &s_bin, &s_krem);
        __syncthreads();
        if (tid == 0) { s_T = (pfx2 << 10) | (unsigned)s_bin; s_allow = s_krem; }
        __syncthreads();
    }
    unsigned T = s_T, allow = s_allow;

    const float* rg; const float* lc; int HW; float sf;
    if (lev == 0)      { rg = r0 + (size_t)n*40000; lc = l0; HW = 10000; sf = 8.0f; }
    else if (lev == 1) { rg = r1 + (size_t)n*10000; lc = l1; HW = 2500;  sf = 16.0f; }
    else               { rg = r2 + (size_t)n*2500;  lc = l2; HW = 625;   sf = 32.0f; }

    for (int i = tid; i < m; i += blockDim.x) {
        unsigned key = keys[i];
        bool take;
        if (m <= KSEL) take = true;
        else {
            take = key > T;
            if (!take && key == T && allow) take = (atomicAdd(&s_tie, 1u) < allow);
        }
        if (!take) continue;
        unsigned slot = atomicAdd(&s_emit, 1u);
        unsigned pos = poss[i];
        int c = (int)pos / HW, hw = (int)pos - c * HW;
        float l = rg[hw]        * sf;
        float t = rg[HW + hw]   * sf;
        float r = rg[2*HW + hw] * sf;
        float b = rg[3*HW + hw] * sf;
        float x = lc[2*hw], y = lc[2*hw + 1];
        float x1 = fminf(fmaxf(x - l, 0.f), 800.f);
        float y1 = fminf(fmaxf(y - t, 0.f), 800.f);
        float x2 = fminf(fmaxf(x + r, 0.f), 800.f);
        float y2 = fminf(fmaxf(y + b, 0.f), 800.f);
        int g = n * NCAND + lev * KSEL + (int)slot;
        g_cbox[g] = make_float4(x1, y1, x2, y2);
        g_csc[g]  = sqrtf(__uint_as_float(key));
        g_ccls[g] = c + 1;
    }
}

// ---------------- greedy NMS (one block per image) ----------------
__global__ __launch_bounds__(1024) void nms_kernel(float* __restrict__ out)
{
    extern __shared__ unsigned char smraw[];
    float* ox1 = (float*)smraw;
    float* oy1 = ox1 + NCAND;
    float* ox2 = oy1 + NCAND;
    float* oy2 = ox2 + NCAND;
    float* oar = oy2 + NCAND;
    float* osc = oar + NCAND;
    int*   ocl = (int*)(osc + NCAND);

    __shared__ float rs[32]; __shared__ int ri[32];
    __shared__ float sB; __shared__ int sI;

    int n = blockIdx.x;
    int tid = threadIdx.x;
    int lane = tid & 31, wid = tid >> 5;

    for (int i = tid; i < NCAND; i += blockDim.x) {
        float s = g_csc[n*NCAND + i];
        float4 b = g_cbox[n*NCAND + i];
        int c = g_ccls[n*NCAND + i];
        float x1, y1, x2, y2, a;
        if (s > 0.f) {
            float off = (float)c * 4096.0f;
            x1 = b.x + off; y1 = b.y + off; x2 = b.z + off; y2 = b.w + off;
            a = (x2 - x1) * (y2 - y1);
        } else {
            s = -1.0f; x1 = y1 = x2 = y2 = a = 0.f;
        }
        ox1[i] = x1; oy1[i] = y1; ox2[i] = x2; oy2[i] = y2;
        oar[i] = a;  osc[i] = s;  ocl[i] = c;
    }
    __syncthreads();

    for (int it = 0; it < NPICK; ++it) {
        float bs = -2.0f; int bi = NCAND;
        for (int i = tid; i < NCAND; i += blockDim.x) {
            float s = osc[i];
            if (s > bs || (s == bs && i < bi)) { bs = s; bi = i; }
        }
        #pragma unroll
        for (int o = 16; o; o >>= 1) {
            float s2 = __shfl_down_sync(0xFFFFFFFFu, bs, o);
            int   i2 = __shfl_down_sync(0xFFFFFFFFu, bi, o);
            if (s2 > bs || (s2 == bs && i2 < bi)) { bs = s2; bi = i2; }
        }
        if (lane == 0) { rs[wid] = bs; ri[wid] = bi; }
        __syncthreads();
        if (wid == 0) {
            float s = rs[lane]; int b = ri[lane];
            #pragma unroll
            for (int o = 16; o; o >>= 1) {
                float s2 = __shfl_down_sync(0xFFFFFFFFu, s, o);
                int   b2 = __shfl_down_sync(0xFFFFFFFFu, b, o);
                if (s2 > s || (s2 == s && b2 < b)) { s = s2; b = b2; }
            }
            if (lane == 0) { sB = s; sI = b; }
        }
        __syncthreads();
        bs = sB; bi = sI;
        bool keep = bs > 0.0f;

        if (tid < 7) {
            int row = n * NPICK + it;
            if (tid < 4)       out[OFS_BOX + row*4 + tid] = keep ? ((const float*)&g_cbox[n*NCAND + bi])[tid] : 0.f;
            else if (tid == 4) out[OFS_SC + row] = keep ? bs : 0.f;
            else if (tid == 5) out[OFS_CL + row] = keep ? (float)ocl[bi] : 0.f;
            else               out[OFS_KP + row] = keep ? 1.0f : 0.f;
        }

        float px1 = ox1[bi], py1 = oy1[bi], px2 = ox2[bi], py2 = oy2[bi], pa = oar[bi];
        for (int i = tid; i < NCAND; i += blockDim.x) {
            if (i == bi) { osc[i] = -1.0f; continue; }
            float xx1 = fmaxf(px1, ox1[i]);
            float yy1 = fmaxf(py1, oy1[i]);
            float xx2 = fminf(px2, ox2[i]);
            float yy2 = fminf(py2, oy2[i]);
            float inter = fmaxf(xx2 - xx1, 0.f) * fmaxf(yy2 - yy1, 0.f);
            float iou = inter / (oar[i] + pa - inter + 1e-9f);
            if (iou > 0.6f) osc[i] = -1.0f;
        }
        __syncthreads();
    }
}

// ---------------- launch ----------------
extern "C" void kernel_launch(void* const* d_in, const int* in_sizes, int n_in,
                              void* d_out, int out_size)
{
    const float *loc0, *loc1, *loc2, *cls0, *cls1, *cls2;
    const float *reg0, *reg1, *reg2, *ctr0, *ctr1, *ctr2;
    if (in_sizes[1] == 16 * 80 * 10000) {
        // dict order: per-level (loc, cls, reg, ctr)
        loc0 = (const float*)d_in[0];  cls0 = (const float*)d_in[1];
        reg0 = (const float*)d_in[2];  ctr0 = (const float*)d_in[3];
        loc1 = (const float*)d_in[4];  cls1 = (const float*)d_in[5];
        reg1 = (const float*)d_in[6];  ctr1 = (const float*)d_in[7];
        loc2 = (const float*)d_in[8];  cls2 = (const float*)d_in[9];
        reg2 = (const float*)d_in[10]; ctr2 = (const float*)d_in[11];
    } else {
        loc0 = (const float*)d_in[0];  loc1 = (const float*)d_in[1];  loc2 = (const float*)d_in[2];
        cls0 = (const float*)d_in[3];  cls1 = (const float*)d_in[4];  cls2 = (const float*)d_in[5];
        reg0 = (const float*)d_in[6];  reg1 = (const float*)d_in[7];  reg2 = (const float*)d_in[8];
        ctr0 = (const float*)d_in[9];  ctr1 = (const float*)d_in[10]; ctr2 = (const float*)d_in[11];
    }
    float* out = (float*)d_out;

    cudaFuncSetAttribute(nms_kernel, cudaFuncAttributeMaxDynamicSharedMemorySize, 7 * NCAND * 4);

    init_kernel<<<416, 256>>>();
    pass1_kernel<<<dim3(64, NIMG), 256>>>(cls0, cls1, cls2, ctr0, ctr1, ctr2);
    select1_kernel<<<NIMG*3, 256>>>();
    collect_kernel<<<dim3(64, NIMG), 256>>>(cls0, cls1, cls2, ctr0, ctr1, ctr2);
    seg_select_kernel<<<NIMG*3, 256>>>(reg0, reg1, reg2, loc0, loc1, loc2);
    nms_kernel<<<NIMG, 1024, 7 * NCAND * 4>>>(out);
}

// round 7
// speedup vs baseline: 2.5457x; 1.1073x over previous
#include <cuda_runtime.h>
#include <math.h>
#include <float.h>

#define NIMG   16
#define KSEL   1000
#define NCAND  3000
#define NPICK  100
#define HWTOT  13125
#define HWPAD  13128
#define MTOT   1050000
#define CAP    131072
#define NB1    4096

// Output layout (float32, concatenated tuple: boxes, scores, classes, keep)
#define OFS_BOX 0
#define OFS_SC  (NIMG*NPICK*4)
#define OFS_CL  (OFS_SC + NIMG*NPICK)
#define OFS_KP  (OFS_CL + NIMG*NPICK)

// ---------------- scratch (device globals, no allocation) ----------------
__device__ float    g_t[NIMG*HWPAD];      // sigmoid(ctr) per location
__device__ float    g_xc0[NIMG*HWPAD];    // static cutoff: x >= xc0 possible score >= 0.5
__device__ float    g_xcF[NIMG*HWPAD];    // per-segment cutoff for F
__device__ unsigned g_h1[NIMG*3*NB1];     // fine hist over [0.5,1)
__device__ unsigned g_h2[NIMG*3*2048];    // fallback coarse hist
__device__ unsigned g_F[NIMG*3];
__device__ unsigned g_fb[NIMG*3];
__device__ unsigned g_colcnt[NIMG*3];
__device__ unsigned g_colkey[(size_t)NIMG*3*CAP];
__device__ unsigned g_colpos[(size_t)NIMG*3*CAP];
__device__ float4   g_cbox[NIMG*NCAND];
__device__ float    g_csc[NIMG*NCAND];
__device__ int      g_ccls[NIMG*NCAND];

__device__ __forceinline__ float fsigm(float x) { return __fdividef(1.0f, 1.0f + __expf(-x)); }

// Conservative x-cutoff: every element whose exact key (= fl(fsigm(x)*t)) can be
// >= Fv satisfies x >= cutval(Fv,t). logf(F/(t-F)) form avoids cancellation;
// margin scales with r to cover fast-math sigmoid error amplification.
__device__ __forceinline__ float cutval(float Fv, float t)
{
    if (!(t > Fv)) return (t == Fv) ? 16.0f : FLT_MAX;  // only s==1.0 could reach
    float r = Fv / (t - Fv);
    if (r > 1.0e6f) return -1000.0f;                    // pass all at this location
    return logf(r) - (0.05f + 5e-6f * r);
}

// ---------------- init: tables + zero scratch ----------------
__global__ void init_kernel(const float* __restrict__ c0, const float* __restrict__ c1,
                            const float* __restrict__ c2)
{
    int i0 = blockIdx.x * blockDim.x + threadIdx.x;
    int st = gridDim.x * blockDim.x;
    for (int j = i0; j < NIMG*3*NB1; j += st) g_h1[j] = 0;
    for (int j = i0; j < NIMG*3*2048; j += st) g_h2[j] = 0;
    for (int j = i0; j < NIMG*3; j += st) g_colcnt[j] = 0;
    for (int j = i0; j < NIMG*NCAND; j += st) {
        g_csc[j] = -1.0f; g_ccls[j] = 0;
        g_cbox[j] = make_float4(0.f, 0.f, 0.f, 0.f);
    }
    for (int j = i0; j < NIMG*HWPAD; j += st) {
        int n = j / HWPAD, r = j - n * HWPAD;
        float t = 0.0f;
        if (r < 10000)      t = fsigm(c0[n*10000 + r]);
        else if (r < 12500) t = fsigm(c1[n*2500  + (r - 10000)]);
        else if (r < HWTOT) t = fsigm(c2[n*625   + (r - 12500)]);
        g_t[j]   = t;
        g_xc0[j] = cutval(0.5f, t);
    }
}

// ---------------- pass 1: filtered fine histogram ----------------
template<int HW, bool VEC>
__device__ __forceinline__ void scan_hist(int e, float4 xv, const float* __restrict__ tb,
                                          const float* __restrict__ cb, unsigned* sh)
{
    float xs[4] = {xv.x, xv.y, xv.z, xv.w};
    if (VEC) {
        int c = e / HW; int hw = e - c*HW;
        float4 cv = *reinterpret_cast<const float4*>(cb + hw);
        float cs[4] = {cv.x, cv.y, cv.z, cv.w};
        #pragma unroll
        for (int j = 0; j < 4; ++j)
            if (xs[j] >= cs[j]) {
                float s = fsigm(xs[j]);
                unsigned key = __float_as_uint(s * tb[hw + j]);
                if (key >= 0x3F000000u) {
                    unsigned b = (key - 0x3F000000u) >> 11;
                    if (b > NB1-1) b = NB1-1;
                    atomicAdd(&sh[b], 1u);
                }
            }
    } else {
        #pragma unroll
        for (int j = 0; j < 4; ++j) {
            int e2 = e + j; int c = e2 / HW; int hw = e2 - c*HW;
            if (xs[j] >= cb[hw]) {
                float s = fsigm(xs[j]);
                unsigned key = __float_as_uint(s * tb[hw]);
                if (key >= 0x3F000000u) {
                    unsigned b = (key - 0x3F000000u) >> 11;
                    if (b > NB1-1) b = NB1-1;
                    atomicAdd(&sh[b], 1u);
                }
            }
        }
    }
}

__global__ __launch_bounds__(256) void pass1_kernel(
    const float* __restrict__ c0, const float* __restrict__ c1, const float* __restrict__ c2)
{
    __shared__ unsigned sh[NB1];
    for (int i = threadIdx.x; i < NB1; i += blockDim.x) sh[i] = 0;
    __syncthreads();

    int n = blockIdx.y, bx = blockIdx.x;
    int lev, b0, nb, vlo, vhi, ctro;
    const float* src;
    if (bx < 48)      { lev = 0; b0 = 0;  nb = 48; vlo = 0;      vhi = 200000; ctro = 0;
                        src = c0 + (size_t)n*800000; }
    else if (bx < 60) { lev = 1; b0 = 48; nb = 12; vlo = 200000; vhi = 250000; ctro = 10000;
                        src = c1 + (size_t)n*200000; }
    else              { lev = 2; b0 = 60; nb = 4;  vlo = 250000; vhi = 262500; ctro = 12500;
                        src = c2 + (size_t)n*50000; }
    const float* tb = g_t   + n*HWPAD + ctro;
    const float* cb = g_xc0 + n*HWPAD + ctro;
    int vstride = nb * blockDim.x;
    int base = vlo * 4;

    for (int v = vlo + (bx - b0)*blockDim.x + threadIdx.x; v < vhi; v += vstride) {
        int e = v*4 - base;
        float4 xv = *reinterpret_cast<const float4*>(src + e);
        if (lev == 0)      scan_hist<10000, true>(e, xv, tb, cb, sh);
        else if (lev == 1) scan_hist<2500, true>(e, xv, tb, cb, sh);
        else               scan_hist<625, false>(e, xv, tb, cb, sh);
    }
    __syncthreads();
    unsigned* gh = g_h1 + (n*3 + lev) * NB1;
    for (int i = threadIdx.x; i < NB1; i += blockDim.x)
        if (sh[i]) atomicAdd(&gh[i], sh[i]);
}

// ---------------- select1: F = floor of bin containing rank-1000 key ----------------
__global__ void select1_kernel()
{
    __shared__ unsigned csum[NB1/32];
    int seg = blockIdx.x, tid = threadIdx.x;
    const unsigned* gh = g_h1 + (size_t)seg * NB1;
    if (tid < NB1/32) {
        unsigned s = 0;
        for (int b = tid*32; b < tid*32 + 32; ++b) s += gh[b];
        csum[tid] = s;
    }
    __syncthreads();
    if (tid == 0) {
        unsigned cum = 0, F = 1; int fb = 1;
        for (int ch = NB1/32 - 1; ch >= 0; --ch) {
            if (cum + csum[ch] >= KSEL) {
                for (int b = ch*32 + 31; ; --b) {
                    cum += gh[b];
                    if (cum >= KSEL) { F = 0x3F000000u | ((unsigned)b << 11); fb = 0; break; }
                }
                break;
            }
            cum += csum[ch];
        }
        g_F[seg] = F; g_fb[seg] = fb;
    }
}

// ---------------- fallback: full coarse histogram + select (normally no-op) ----------
__global__ __launch_bounds__(256) void fb_hist_kernel(
    const float* __restrict__ c0, const float* __restrict__ c1, const float* __restrict__ c2)
{
    int n = blockIdx.y, bx = blockIdx.x;
    int lev, b0, nb, vlo, vhi, ctro;
    const float* src;
    if (bx < 48)      { lev = 0; b0 = 0;  nb = 48; vlo = 0;      vhi = 200000; ctro = 0;
                        src = c0 + (size_t)n*800000; }
    else if (bx < 60) { lev = 1; b0 = 48; nb = 12; vlo = 200000; vhi = 250000; ctro = 10000;
                        src = c1 + (size_t)n*200000; }
    else              { lev = 2; b0 = 60; nb = 4;  vlo = 250000; vhi = 262500; ctro = 12500;
                        src = c2 + (size_t)n*50000; }
    int seg = n*3 + lev;
    if (!g_fb[seg]) return;

    __shared__ unsigned sh[2048];
    for (int i = threadIdx.x; i < 2048; i += blockDim.x) sh[i] = 0;
    __syncthreads();
    const float* tb = g_t + n*HWPAD + ctro;
    int HW = lev == 0 ? 10000 : (lev == 1 ? 2500 : 625);
    int vstride = nb * blockDim.x;
    int base = vlo * 4;
    for (int v = vlo + (bx - b0)*blockDim.x + threadIdx.x; v < vhi; v += vstride) {
        int e = v*4 - base;
        float4 xv = *reinterpret_cast<const float4*>(src + e);
        float xs[4] = {xv.x, xv.y, xv.z, xv.w};
        #pragma unroll
        for (int j = 0; j < 4; ++j) {
            int e2 = e + j; int c = e2 / HW; int hw = e2 - c*HW;
            float s = fsigm(xs[j]);
            if (s > 0.05f) {
                unsigned key = __float_as_uint(s * tb[hw]);
                if (key) atomicAdd(&sh[key >> 21], 1u);
            }
        }
    }
    __syncthreads();
    unsigned* gh = g_h2 + (size_t)seg * 2048;
    for (int i = threadIdx.x; i < 2048; i += blockDim.x)
        if (sh[i]) atomicAdd(&gh[i], sh[i]);
}

__global__ void fb_select_kernel()
{
    int seg = blockIdx.x;
    if (!g_fb[seg]) return;
    __shared__ unsigned csum[64];
    int tid = threadIdx.x;
    const unsigned* gh = g_h2 + (size_t)seg * 2048;
    if (tid < 64) {
        unsigned s = 0;
        for (int b = tid*32; b < tid*32 + 32; ++b) s += gh[b];
        csum[tid] = s;
    }
    __syncthreads();
    if (tid == 0) {
        unsigned cum = 0, F = 1;
        for (int ch = 63; ch >= 0; --ch) {
            if (cum + csum[ch] >= KSEL) {
                for (int b = ch*32 + 31; ; --b) {
                    cum += gh[b];
                    if (cum >= KSEL) { F = ((unsigned)b) << 21; if (F == 0) F = 1; break; }
                }
                break;
            }
            cum += csum[ch];
        }
        g_F[seg] = F;
    }
}

// ---------------- xcutF: per-location collect cutoff ----------------
__global__ void xcutF_kernel()
{
    int i0 = blockIdx.x * blockDim.x + threadIdx.x;
    int st = gridDim.x * blockDim.x;
    for (int j = i0; j < NIMG*HWPAD; j += st) {
        int n = j / HWPAD, r = j - n * HWPAD;
        if (r >= HWTOT) { g_xcF[j] = FLT_MAX; continue; }
        int lev = r < 10000 ? 0 : (r < 12500 ? 1 : 2);
        float Fv = __uint_as_float(g_F[n*3 + lev]);
        g_xcF[j] = cutval(Fv, g_t[j]);
    }
}

// ---------------- collect: filtered exact append ----------------
template<int HW, bool VEC>
__device__ __forceinline__ void scan_collect(int e, float4 xv, const float* __restrict__ tb,
                                             const float* __restrict__ cb, unsigned F, int seg,
                                             unsigned lane)
{
    float xs[4] = {xv.x, xv.y, xv.z, xv.w};
    float cs[4];
    int hwb = 0;
    if (VEC) {
        int c = e / HW; hwb = e - c*HW;
        float4 cv = *reinterpret_cast<const float4*>(cb + hwb);
        cs[0] = cv.x; cs[1] = cv.y; cs[2] = cv.z; cs[3] = cv.w;
    }
    #pragma unroll
    for (int j = 0; j < 4; ++j) {
        bool take = false; unsigned key = 0;
        int hw;
        if (VEC) hw = hwb + j;
        else { int e2 = e + j; int c = e2 / HW; hw = e2 - c*HW; }
        float cut = VEC ? cs[j] : cb[hw];
        if (xs[j] >= cut) {
            float s = fsigm(xs[j]);
            key = (s > 0.05f) ? __float_as_uint(s * tb[hw]) : 0u;
            take = key >= F;
        }
        unsigned mask = __activemask();
        unsigned bal = __ballot_sync(mask, take);
        if (take) {
            int leader = __ffs(bal) - 1;
            unsigned rank = __popc(bal & ((1u << lane) - 1u));
            unsigned basep = 0;
            if ((int)lane == leader)
                basep = atomicAdd(&g_colcnt[seg], (unsigned)__popc(bal));
            basep = __shfl_sync(bal, basep, leader);
            unsigned idx = basep + rank;
            if (idx < CAP) {
                g_colkey[(size_t)seg*CAP + idx] = key;
                g_colpos[(size_t)seg*CAP + idx] = (unsigned)(e + j);
            }
        }
    }
}

__global__ __launch_bounds__(256) void collect_kernel(
    const float* __restrict__ c0, const float* __restrict__ c1, const float* __restrict__ c2)
{
    int n = blockIdx.y, bx = blockIdx.x;
    int lev, b0, nb, vlo, vhi, ctro;
    const float* src;
    if (bx < 48)      { lev = 0; b0 = 0;  nb = 48; vlo = 0;      vhi = 200000; ctro = 0;
                        src = c0 + (size_t)n*800000; }
    else if (bx < 60) { lev = 1; b0 = 48; nb = 12; vlo = 200000; vhi = 250000; ctro = 10000;
                        src = c1 + (size_t)n*200000; }
    else              { lev = 2; b0 = 60; nb = 4;  vlo = 250000; vhi = 262500; ctro = 12500;
                        src = c2 + (size_t)n*50000; }
    int seg = n*3 + lev;
    unsigned F = g_F[seg];
    const float* tb = g_t   + n*HWPAD + ctro;
    const float* cb = g_xcF + n*HWPAD + ctro;
    int vstride = nb * blockDim.x;
    int base = vlo * 4;
    unsigned lane = threadIdx.x & 31;

    for (int v = vlo + (bx - b0)*blockDim.x + threadIdx.x; v < vhi; v += vstride) {
        int e = v*4 - base;
        float4 xv = *reinterpret_cast<const float4*>(src + e);
        if (lev == 0)      scan_collect<10000, true>(e, xv, tb, cb, F, seg, lane);
        else if (lev == 1) scan_collect<2500, true>(e, xv, tb, cb, F, seg, lane);
        else               scan_collect<625, false>(e, xv, tb, cb, F, seg, lane);
    }
}

// ---------------- block-level histogram select (descending) ----------------
__device__ __forceinline__ void bsel(unsigned* sh, int nb, unsigned target,
                                     int* r_bin, unsigned* r_krem)
{
    __shared__ unsigned gsum[64];
    int tid = threadIdx.x;
    int ngroups = nb / 32;
    if (tid < ngroups) {
        unsigned s = 0;
        for (int j = 0; j < 32; ++j) s += sh[tid*32 + j];
        gsum[tid] = s;
    }
    __syncthreads();
    if (tid == 0) {
        unsigned cum = 0;
        *r_bin = 0; *r_krem = target;
        for (int g = ngroups - 1; g >= 0; --g) {
            if (cum + gsum[g] >= target) {
                for (int b = g*32 + 31; b >= g*32; --b) {
                    if (cum + sh[b] >= target) { *r_bin = b; *r_krem = target - cum; return; }
                    cum += sh[b];
                }
            }
            cum += gsum[g];
        }
    }
}

// ---------------- seg_select: exact top-1000 within collected list + decode ------------
__global__ void seg_select_kernel(const float* __restrict__ r0, const float* __restrict__ r1,
                                  const float* __restrict__ r2, const float* __restrict__ l0,
                                  const float* __restrict__ l1, const float* __restrict__ l2)
{
    __shared__ unsigned sh[2048];
    __shared__ int s_bin; __shared__ unsigned s_krem;
    __shared__ unsigned s_T, s_allow, s_emit, s_tie;
    int seg = blockIdx.x;
    int n = seg / 3, lev = seg % 3;
    unsigned mraw = g_colcnt[seg];
    int m = (int)(mraw < CAP ? mraw : CAP);
    const unsigned* keys = g_colkey + (size_t)seg*CAP;
    const unsigned* poss = g_colpos + (size_t)seg*CAP;
    int tid = threadIdx.x;

    if (tid == 0) { s_emit = 0; s_tie = 0; }

    if (m <= KSEL) {
        if (tid == 0) { s_T = 0; s_allow = 0; }
        __syncthreads();
    } else {
        for (int i = tid; i < 2048; i += blockDim.x) sh[i] = 0;
        __syncthreads();
        for (int i = tid; i < m; i += blockDim.x)
            atomicAdd(&sh[keys[i] >> 21], 1u);
        __syncthreads();
        bsel(sh, 2048, KSEL, &s_bin, &s_krem);
        __syncthreads();
        unsigned b1 = (unsigned)s_bin, want = s_krem;
        __syncthreads();
        for (int i = tid; i < 2048; i += blockDim.x) sh[i] = 0;
        __syncthreads();
        for (int i = tid; i < m; i += blockDim.x) {
            unsigned key = keys[i];
            if ((key >> 21) == b1) atomicAdd(&sh[(key >> 10) & 0x7FF], 1u);
        }
        __syncthreads();
        bsel(sh, 2048, want, &s_bin, &s_krem);
        __syncthreads();
        unsigned b2 = (unsigned)s_bin; want = s_krem;
        unsigned pfx2 = (b1 << 11) | b2;
        __syncthreads();
        for (int i = tid; i < 1024; i += blockDim.x) sh[i] = 0;
        __syncthreads();
        for (int i = tid; i < m; i += blockDim.x) {
            unsigned key = keys[i];
            if ((key >> 10) == pfx2) atomicAdd(&sh[key & 0x3FF], 1u);
        }
        __syncthreads();
        bsel(sh, 1024, want, &s_bin, &s_krem);
        __syncthreads();
        if (tid == 0) { s_T = (pfx2 << 10) | (unsigned)s_bin; s_allow = s_krem; }
        __syncthreads();
    }
    unsigned T = s_T, allow = s_allow;

    const float* rg; const float* lc; int HW; float sf;
    if (lev == 0)      { rg = r0 + (size_t)n*40000; lc = l0; HW = 10000; sf = 8.0f; }
    else if (lev == 1) { rg = r1 + (size_t)n*10000; lc = l1; HW = 2500;  sf = 16.0f; }
    else               { rg = r2 + (size_t)n*2500;  lc = l2; HW = 625;   sf = 32.0f; }

    for (int i = tid; i < m; i += blockDim.x) {
        unsigned key = keys[i];
        bool take;
        if (m <= KSEL) take = true;
        else {
            take = key > T;
            if (!take && key == T && allow) take = (atomicAdd(&s_tie, 1u) < allow);
        }
        if (!take) continue;
        unsigned slot = atomicAdd(&s_emit, 1u);
        unsigned pos = poss[i];
        int c = (int)pos / HW, hw = (int)pos - c * HW;
        float l = rg[hw]        * sf;
        float t = rg[HW + hw]   * sf;
        float r = rg[2*HW + hw] * sf;
        float b = rg[3*HW + hw] * sf;
        float x = lc[2*hw], y = lc[2*hw + 1];
        float x1 = fminf(fmaxf(x - l, 0.f), 800.f);
        float y1 = fminf(fmaxf(y - t, 0.f), 800.f);
        float x2 = fminf(fmaxf(x + r, 0.f), 800.f);
        float y2 = fminf(fmaxf(y + b, 0.f), 800.f);
        int g = n * NCAND + lev * KSEL + (int)slot;
        g_cbox[g] = make_float4(x1, y1, x2, y2);
        g_csc[g]  = sqrtf(__uint_as_float(key));
        g_ccls[g] = c + 1;
    }
}

// ---------------- greedy NMS: register-resident scores, fused suppress+scan ------------
__global__ __launch_bounds__(1024) void nms_kernel(float* __restrict__ out)
{
    extern __shared__ unsigned char smraw[];
    float* sx1 = (float*)smraw;
    float* sy1 = sx1 + NCAND;
    float* sx2 = sy1 + NCAND;
    float* sy2 = sx2 + NCAND;
    float* sar = sy2 + NCAND;
    int*   scl = (int*)(sar + NCAND);

    __shared__ float rs[32]; __shared__ int ri[32];
    __shared__ float sB; __shared__ int sI;

    int n = blockIdx.x;
    int tid = threadIdx.x;
    int lane = tid & 31, wid = tid >> 5;

    float sc[3], bx1[3], by1[3], bx2[3], by2[3], ba[3];
    #pragma unroll
    for (int k = 0; k < 3; ++k) {
        int i = tid + k * 1024;
        float s = -2.0f, x1 = 0.f, y1 = 0.f, x2 = 0.f, y2 = 0.f, a = 0.f;
        if (i < NCAND) {
            s = g_csc[n*NCAND + i];
            float4 b = g_cbox[n*NCAND + i];
            int c = g_ccls[n*NCAND + i];
            if (s > 0.f) {
                float off = (float)c * 4096.0f;
                x1 = b.x + off; y1 = b.y + off; x2 = b.z + off; y2 = b.w + off;
                a = (x2 - x1) * (y2 - y1);
            } else s = -1.0f;
            sx1[i] = x1; sy1[i] = y1; sx2[i] = x2; sy2[i] = y2; sar[i] = a; scl[i] = c;
        }
        sc[k] = s; bx1[k] = x1; by1[k] = y1; bx2[k] = x2; by2[k] = y2; ba[k] = a;
    }
    __syncthreads();

    for (int it = 0; it < NPICK; ++it) {
        float bs = -3.0f; int bi = 0x7FFFFFFF;
        #pragma unroll
        for (int k = 0; k < 3; ++k)
            if (sc[k] > bs) { bs = sc[k]; bi = tid + k*1024; }
        #pragma unroll
        for (int o = 16; o; o >>= 1) {
            float s2 = __shfl_down_sync(0xFFFFFFFFu, bs, o);
            int   i2 = __shfl_down_sync(0xFFFFFFFFu, bi, o);
            if (s2 > bs || (s2 == bs && i2 < bi)) { bs = s2; bi = i2; }
        }
        if (lane == 0) { rs[wid] = bs; ri[wid] = bi; }
        __syncthreads();
        if (wid == 0) {
            float s = rs[lane]; int b = ri[lane];
            #pragma unroll
            for (int o = 16; o; o >>= 1) {
                float s2 = __shfl_down_sync(0xFFFFFFFFu, s, o);
                int   b2 = __shfl_down_sync(0xFFFFFFFFu, b, o);
                if (s2 > s || (s2 == s && b2 < b)) { s = s2; b = b2; }
            }
            if (lane == 0) { sB = s; sI = b; }
        }
        __syncthreads();
        float pbs = sB; int pbi = sI;
        bool keep = pbs > 0.0f;

        if (tid < 7) {
            int row = n * NPICK + it;
            if (tid < 4)       out[OFS_BOX + row*4 + tid] = keep ? ((const float*)&g_cbox[n*NCAND + pbi])[tid] : 0.f;
            else if (tid == 4) out[OFS_SC + row] = keep ? pbs : 0.f;
            else if (tid == 5) out[OFS_CL + row] = keep ? (float)scl[pbi] : 0.f;
            else               out[OFS_KP + row] = keep ? 1.0f : 0.f;
        }

        float px1 = sx1[pbi], py1 = sy1[pbi], px2 = sx2[pbi], py2 = sy2[pbi], pa = sar[pbi];
        #pragma unroll
        for (int k = 0; k < 3; ++k) {
            if (tid + k*1024 == pbi) { sc[k] = -1.0f; continue; }
            float xx1 = fmaxf(px1, bx1[k]);
            float yy1 = fmaxf(py1, by1[k]);
            float xx2 = fminf(px2, bx2[k]);
            float yy2 = fminf(py2, by2[k]);
            float inter = fmaxf(xx2 - xx1, 0.f) * fmaxf(yy2 - yy1, 0.f);
            float iou = inter / (ba[k] + pa - inter + 1e-9f);
            if (iou > 0.6f && sc[k] > -1.5f) sc[k] = -1.0f;
        }
    }
}

// ---------------- launch ----------------
extern "C" void kernel_launch(void* const* d_in, const int* in_sizes, int n_in,
                              void* d_out, int out_size)
{
    const float *loc0, *loc1, *loc2, *cls0, *cls1, *cls2;
    const float *reg0, *reg1, *reg2, *ctr0, *ctr1, *ctr2;
    if (in_sizes[1] == 16 * 80 * 10000) {
        loc0 = (const float*)d_in[0];  cls0 = (const float*)d_in[1];
        reg0 = (const float*)d_in[2];  ctr0 = (const float*)d_in[3];
        loc1 = (const float*)d_in[4];  cls1 = (const float*)d_in[5];
        reg1 = (const float*)d_in[6];  ctr1 = (const float*)d_in[7];
        loc2 = (const float*)d_in[8];  cls2 = (const float*)d_in[9];
        reg2 = (const float*)d_in[10]; ctr2 = (const float*)d_in[11];
    } else {
        loc0 = (const float*)d_in[0];  loc1 = (const float*)d_in[1];  loc2 = (const float*)d_in[2];
        cls0 = (const float*)d_in[3];  cls1 = (const float*)d_in[4];  cls2 = (const float*)d_in[5];
        reg0 = (const float*)d_in[6];  reg1 = (const float*)d_in[7];  reg2 = (const float*)d_in[8];
        ctr0 = (const float*)d_in[9];  ctr1 = (const float*)d_in[10]; ctr2 = (const float*)d_in[11];
    }
    float* out = (float*)d_out;

    cudaFuncSetAttribute(nms_kernel, cudaFuncAttributeMaxDynamicSharedMemorySize, 6 * NCAND * 4);

    init_kernel<<<416, 256>>>(ctr0, ctr1, ctr2);
    pass1_kernel<<<dim3(64, NIMG), 256>>>(cls0, cls1, cls2);
    select1_kernel<<<NIMG*3, 256>>>();
    fb_hist_kernel<<<dim3(64, NIMG), 256>>>(cls0, cls1, cls2);
    fb_select_kernel<<<NIMG*3, 256>>>();
    xcutF_kernel<<<256, 256>>>();
    collect_kernel<<<dim3(64, NIMG), 256>>>(cls0, cls1, cls2);
    seg_select_kernel<<<NIMG*3, 256>>>(reg0, reg1, reg2, loc0, loc1, loc2);
    nms_kernel<<<NIMG, 1024, 6 * NCAND * 4>>>(out);
}